// round 7
// baseline (speedup 1.0000x reference)
#include <cuda_runtime.h>
#include <math.h>
#include <stdint.h>

#define NB 2
#define SQ 2048
#define NTOK 4096
#define DM 512
#define NH 8
#define DK 64
#define NL 6
#define DFF 2048
#define NV 1024
#define QKVW 1536

// ---------------- scratch ----------------
__device__ float   g_x  [NTOK * DM];
__device__ float   g_h  [NTOK * DM];
__device__ float   g_qkv[NTOK * QKVW];
__device__ float   g_ff [NTOK * DFF];
__device__ int8_t  g_ah8[NTOK * DFF];
__device__ int8_t  g_al8[NTOK * DFF];
__device__ float   g_sa [NTOK];
__device__ int8_t  g_wqkv_h[NL * QKVW * DM]; __device__ int8_t g_wqkv_l[NL * QKVW * DM];
__device__ int8_t  g_wo_h [NL * DM * DM];    __device__ int8_t g_wo_l [NL * DM * DM];
__device__ int8_t  g_w1_h [NL * DFF * DM];   __device__ int8_t g_w1_l [NL * DFF * DM];
__device__ int8_t  g_w2_h [NL * DM * DFF];   __device__ int8_t g_w2_l [NL * DM * DFF];
__device__ int8_t  g_ow_h [NV * DM];         __device__ int8_t g_ow_l [NV * DM];
__device__ float   g_sbqkv[NL * QKVW], g_sbo[NL * DM], g_sb1[NL * DFF];
__device__ float   g_sb2[NL * DM], g_sow[NV], g_bqkv[NL * QKVW];

// ---------------- helpers ----------------
__device__ __forceinline__ uint32_t f2tf(float f) {
    uint32_t r;
    asm("cvt.rna.tf32.f32 %0, %1;" : "=r"(r) : "f"(f));
    return r;
}
__device__ __forceinline__ float tfround(float f) { return __uint_as_float(f2tf(f)); }
__device__ __forceinline__ void mma8(float* c, const uint32_t* a, const uint32_t* b) {
    asm volatile(
        "mma.sync.aligned.m16n8k8.row.col.f32.tf32.tf32.f32 "
        "{%0,%1,%2,%3}, {%4,%5,%6,%7}, {%8,%9}, {%0,%1,%2,%3};\n"
        : "+f"(c[0]), "+f"(c[1]), "+f"(c[2]), "+f"(c[3])
        : "r"(a[0]), "r"(a[1]), "r"(a[2]), "r"(a[3]), "r"(b[0]), "r"(b[1]));
}
__device__ __forceinline__ void imma_ss(int* c, const uint32_t* a, const uint32_t* b) {
    asm volatile(
        "mma.sync.aligned.m16n8k32.row.col.s32.s8.s8.s32 "
        "{%0,%1,%2,%3}, {%4,%5,%6,%7}, {%8,%9}, {%0,%1,%2,%3};\n"
        : "+r"(c[0]), "+r"(c[1]), "+r"(c[2]), "+r"(c[3])
        : "r"(a[0]), "r"(a[1]), "r"(a[2]), "r"(a[3]), "r"(b[0]), "r"(b[1]));
}
__device__ __forceinline__ void cpa16(uint32_t dst, const void* src) {
    asm volatile("cp.async.cg.shared.global [%0], [%1], 16;" :: "r"(dst), "l"(src));
}
#define CP_COMMIT() asm volatile("cp.async.commit_group;" ::: "memory")
#define CP_WAIT(n)  asm volatile("cp.async.wait_group %0;" :: "n"(n) : "memory")
__device__ __forceinline__ uint32_t smem_u32(const void* p) {
    uint32_t a;
    asm("{ .reg .u64 t; cvta.to.shared.u64 t, %1; cvt.u32.u64 %0, t; }" : "=r"(a) : "l"(p));
    return a;
}
__device__ __forceinline__ void qsplit(int q, int8_t& hi, int8_t& lo) {
    int h = (q + 128) >> 8;           // arithmetic shift, round-to-nearest on hi
    hi = (int8_t)h;
    lo = (int8_t)(q - (h << 8));      // in [-128, 127]
}

// ---------------- int8 split GEMM ----------------
// C = (sa[r]*sb[c]) * (65536*hh + 256*(h*l + l*h)) + bias. k-chunk 64 bytes.
#define QPITCH 80
#define QREG  10240
#define QST   40960
#define QSMEM (3 * QST)

__global__ __launch_bounds__(256) void gemm_i8(
    const int8_t* __restrict__ Ah, const int8_t* __restrict__ Al,
    const int8_t* __restrict__ Bh, const int8_t* __restrict__ Bl,
    const float* __restrict__ sa, const float* __restrict__ sbv,
    const float* __restrict__ bias, const float* __restrict__ R,
    float* __restrict__ C, int K, int M, int mode)   // 0:plain 1:relu 2:tf32-round
{
    extern __shared__ uint8_t sm8[];
    uint32_t sb32 = smem_u32(sm8);
    int t = threadIdx.x, lane = t & 31, wid = t >> 5;
    int wm = wid & 1, wn = wid >> 1;
    int gr = lane >> 2, tg = lane & 3;
    int row0 = blockIdx.y * 128, col0 = blockIdx.x * 128;
    const int NC = K >> 6;

    int reg = t >> 6, li = t & 63;
    const uint8_t* gbase;
    if (reg == 0)      gbase = (const uint8_t*)Ah + (size_t)row0 * K;
    else if (reg == 1) gbase = (const uint8_t*)Al + (size_t)row0 * K;
    else if (reg == 2) gbase = (const uint8_t*)Bh + (size_t)col0 * K;
    else               gbase = (const uint8_t*)Bl + (size_t)col0 * K;

    int acc1[4][4][4], acc2[4][4][4];
    #pragma unroll
    for (int i = 0; i < 4; i++)
        #pragma unroll
        for (int j = 0; j < 4; j++)
            #pragma unroll
            for (int k = 0; k < 4; k++) { acc1[i][j][k] = 0; acc2[i][j][k] = 0; }

    auto issue = [&](int c, int st) {
        uint32_t dbase = sb32 + st * QST + reg * QREG;
        const uint8_t* s0 = gbase + c * 64;
        #pragma unroll
        for (int j = 0; j < 8; j++) {
            int seg = j * 64 + li, r = seg >> 2, p = seg & 3;
            cpa16(dbase + r * QPITCH + p * 16, s0 + (size_t)r * K + p * 16);
        }
    };

    issue(0, 0); CP_COMMIT();
    if (NC > 1) { issue(1, 1); CP_COMMIT(); }

    for (int c = 0; c < NC; c++) {
        if (c + 1 < NC) { CP_WAIT(1); } else { CP_WAIT(0); }
        __syncthreads();
        if (c + 2 < NC) { issue(c + 2, (c + 2) % 3); CP_COMMIT(); }

        const uint8_t* S = sm8 + (c % 3) * QST;
        const uint32_t* sAh = (const uint32_t*)S;
        const uint32_t* sAl = (const uint32_t*)(S + QREG);
        const uint32_t* sBh = (const uint32_t*)(S + 2 * QREG);
        const uint32_t* sBl = (const uint32_t*)(S + 3 * QREG);
        #pragma unroll
        for (int ks = 0; ks < 2; ks++) {
            int cb = ks * 8;
            uint32_t ah[4][4], al[4][4], bh[4][2], bl[4][2];
            #pragma unroll
            for (int mt = 0; mt < 4; mt++) {
                int r = wm * 64 + mt * 16 + gr;
                const uint32_t* p = sAh + r * 20 + cb + tg;
                ah[mt][0] = p[0]; ah[mt][1] = p[160]; ah[mt][2] = p[4]; ah[mt][3] = p[164];
                const uint32_t* q = sAl + r * 20 + cb + tg;
                al[mt][0] = q[0]; al[mt][1] = q[160]; al[mt][2] = q[4]; al[mt][3] = q[164];
            }
            #pragma unroll
            for (int nt = 0; nt < 4; nt++) {
                int r = wn * 32 + nt * 8 + gr;
                const uint32_t* p = sBh + r * 20 + cb + tg;
                bh[nt][0] = p[0]; bh[nt][1] = p[4];
                const uint32_t* q = sBl + r * 20 + cb + tg;
                bl[nt][0] = q[0]; bl[nt][1] = q[4];
            }
            #pragma unroll
            for (int mt = 0; mt < 4; mt++)
                #pragma unroll
                for (int nt = 0; nt < 4; nt++) {
                    imma_ss(acc1[mt][nt], ah[mt], bh[nt]);
                    imma_ss(acc2[mt][nt], ah[mt], bl[nt]);
                    imma_ss(acc2[mt][nt], al[mt], bh[nt]);
                }
        }
    }

    #pragma unroll
    for (int mt = 0; mt < 4; mt++) {
        int r = row0 + wm * 64 + mt * 16 + gr;
        float sar[2] = { sa[r], sa[r + 8] };
        #pragma unroll
        for (int nt = 0; nt < 4; nt++) {
            int cc = col0 + wn * 32 + nt * 8 + tg * 2;
            float sc0 = sbv[cc], sc1 = sbv[cc + 1];
            float b0 = bias[cc], b1 = bias[cc + 1];
            #pragma unroll
            for (int h2 = 0; h2 < 2; h2++) {
                int rr = r + h2 * 8;
                size_t off = (size_t)rr * M + cc;
                float v0 = sar[h2] * sc0 *
                    fmaf(65536.f, (float)acc1[mt][nt][h2 * 2 + 0], 256.f * (float)acc2[mt][nt][h2 * 2 + 0]) + b0;
                float v1 = sar[h2] * sc1 *
                    fmaf(65536.f, (float)acc1[mt][nt][h2 * 2 + 1], 256.f * (float)acc2[mt][nt][h2 * 2 + 1]) + b1;
                if (R) { float2 rv = *(const float2*)(R + off); v0 += rv.x; v1 += rv.y; }
                if (mode == 1) { v0 = fmaxf(v0, 0.f); v1 = fmaxf(v1, 0.f); }
                if (mode == 2) { v0 = tfround(v0); v1 = tfround(v1); }
                *(float2*)(C + off) = make_float2(v0, v1);
            }
        }
    }
}

// ---------------- flash attention: R5-validated patterns, raw-bit staging ----------------
#define AP 68
#define ATTN_SMEM ((3 * 64 * AP + 192) * 4)

__global__ __launch_bounds__(128) void attn_mma(const float* __restrict__ qkv,
                                                float* __restrict__ out) {
    extern __shared__ uint32_t smu[];
    uint32_t* Qs = smu;
    uint32_t* Ks = smu + 64 * AP;
    float*    Ps = (float*)(smu + 2 * 64 * AP);
    float*  sm_m = (float*)(smu + 3 * 64 * AP);
    float*  sm_l = sm_m + 64;
    float* sm_rs = sm_m + 128;

    int qt = blockIdx.x, bh = blockIdx.y, bb = bh >> 3, hh = bh & 7;
    int t = threadIdx.x, lane = t & 31, wid = t >> 5;
    int gr = lane >> 2, lc = lane & 3;
    int mrow = wid * 16 + gr;
    const size_t base = (size_t)bb * SQ * QKVW + hh * DK;

    // Q row-major (values pre-rounded to tf32 by QKV-GEMM epilogue)
    const float* qb = qkv + base + (size_t)qt * 64 * QKVW;
    #pragma unroll
    for (int i = 0; i < 8; i++) {
        int f = i * 128 + t, r = f >> 4, d4 = (f & 15) << 2;
        *(uint4*)(Qs + r * AP + d4) = *(const uint4*)(qb + (size_t)r * QKVW + d4);
    }
    if (t < 64) { sm_m[t] = -1e30f; sm_l[t] = 0.f; }

    float co[8][4];
    #pragma unroll
    for (int i = 0; i < 8; i++)
        #pragma unroll
        for (int j = 0; j < 4; j++) co[i][j] = 0.f;

    for (int kt = 0; kt <= qt; kt++) {
        __syncthreads();
        // K row-major
        const float* kb = qkv + base + 512 + (size_t)kt * 64 * QKVW;
        #pragma unroll
        for (int i = 0; i < 8; i++) {
            int f = i * 128 + t, r = f >> 4, d4 = (f & 15) << 2;
            *(uint4*)(Ks + r * AP + d4) = *(const uint4*)(kb + (size_t)r * QKVW + d4);
        }
        __syncthreads();

        // S = Q K^T
        float cs[8][4];
        #pragma unroll
        for (int i = 0; i < 8; i++)
            #pragma unroll
            for (int j = 0; j < 4; j++) cs[i][j] = 0.f;
        {
            const uint32_t* Abase = Qs + mrow * AP + lc;
            const uint32_t* Bbase = Ks + gr * AP + lc;
            #pragma unroll
            for (int ks = 0; ks < 8; ks++) {
                uint32_t a[4];
                const uint32_t* p = Abase + ks * 8;
                a[0] = p[0]; a[1] = p[8 * AP]; a[2] = p[4]; a[3] = p[8 * AP + 4];
                #pragma unroll
                for (int nt = 0; nt < 8; nt++) {
                    const uint32_t* q2 = Bbase + nt * 8 * AP + ks * 8;
                    uint32_t b[2] = {q2[0], q2[4]};
                    mma8(cs[nt], a, b);
                }
            }
        }
        #pragma unroll
        for (int nt = 0; nt < 8; nt++) {
            int c = nt * 8 + lc * 2;
            *(float2*)(Ps + mrow * AP + c)       = make_float2(cs[nt][0], cs[nt][1]);
            *(float2*)(Ps + (mrow + 8) * AP + c) = make_float2(cs[nt][2], cs[nt][3]);
        }
        __syncthreads();

        // online softmax (thread-pair per row)
        {
            int r = t >> 1, half = t & 1;
            int qrow = qt * 64 + r;
            int kbase0 = kt * 64 + half * 32;
            float* rowp = Ps + r * AP + half * 32;
            float vals[32];
            float mx = -1e30f;
            bool edge = (kt == qt);
            #pragma unroll
            for (int j = 0; j < 32; j += 4) {
                float4 v4 = *(const float4*)(rowp + j);
                float w0 = v4.x * 0.125f, w1 = v4.y * 0.125f;
                float w2 = v4.z * 0.125f, w3 = v4.w * 0.125f;
                if (edge) {
                    if (kbase0 + j + 0 > qrow) w0 = -1e30f;
                    if (kbase0 + j + 1 > qrow) w1 = -1e30f;
                    if (kbase0 + j + 2 > qrow) w2 = -1e30f;
                    if (kbase0 + j + 3 > qrow) w3 = -1e30f;
                }
                vals[j] = w0; vals[j+1] = w1; vals[j+2] = w2; vals[j+3] = w3;
                mx = fmaxf(mx, fmaxf(fmaxf(w0, w1), fmaxf(w2, w3)));
            }
            mx = fmaxf(mx, __shfl_xor_sync(0xffffffffu, mx, 1));
            float mo = sm_m[r];
            float mn = fmaxf(mo, mx);
            float rs = __expf(mo - mn);
            float ssum = 0.f;
            #pragma unroll
            for (int j = 0; j < 32; j += 4) {
                float p0 = __expf(vals[j]   - mn), p1 = __expf(vals[j+1] - mn);
                float p2 = __expf(vals[j+2] - mn), p3 = __expf(vals[j+3] - mn);
                ssum += (p0 + p1) + (p2 + p3);
                *(uint4*)(rowp + j) = make_uint4(f2tf(p0), f2tf(p1), f2tf(p2), f2tf(p3));
            }
            ssum += __shfl_xor_sync(0xffffffffu, ssum, 1);
            if (!half) { sm_l[r] = sm_l[r] * rs + ssum; sm_m[r] = mn; sm_rs[r] = rs; }
        }

        // V transposed [d][kk]
        const float* vb = qkv + base + 1024 + (size_t)kt * 64 * QKVW;
        #pragma unroll
        for (int i = 0; i < 8; i++) {
            int kk = t & 63;
            int d4 = (i * 2 + (t >> 6)) * 4;
            uint4 v = *(const uint4*)(vb + (size_t)kk * QKVW + d4);
            Ks[(d4 + 0) * AP + kk] = v.x;
            Ks[(d4 + 1) * AP + kk] = v.y;
            Ks[(d4 + 2) * AP + kk] = v.z;
            Ks[(d4 + 3) * AP + kk] = v.w;
        }
        __syncthreads();

        // O = O*rs + P V   (R5-validated fragment pattern)
        {
            float rs0 = sm_rs[mrow], rs1 = sm_rs[mrow + 8];
            #pragma unroll
            for (int nt = 0; nt < 8; nt++) {
                co[nt][0] *= rs0; co[nt][1] *= rs0;
                co[nt][2] *= rs1; co[nt][3] *= rs1;
            }
            const uint32_t* Pb = (const uint32_t*)Ps + mrow * AP + lc;
            const uint32_t* Bbase = Ks + gr * AP + lc;
            #pragma unroll
            for (int ks = 0; ks < 8; ks++) {
                uint32_t a[4];
                const uint32_t* p = Pb + ks * 8;
                a[0] = p[0]; a[1] = p[8 * AP]; a[2] = p[4]; a[3] = p[8 * AP + 4];
                #pragma unroll
                for (int nt = 0; nt < 8; nt++) {
                    const uint32_t* q2 = Bbase + nt * 8 * AP + ks * 8;
                    uint32_t b[2] = {q2[0], q2[4]};
                    mma8(co[nt], a, b);
                }
            }
        }
    }

    float inv0 = 1.f / sm_l[mrow], inv1 = 1.f / sm_l[mrow + 8];
    float* ob = out + ((size_t)bb * SQ + (size_t)qt * 64) * DM + hh * DK;
    #pragma unroll
    for (int nt = 0; nt < 8; nt++) {
        int c = nt * 8 + lc * 2;
        *(float2*)(ob + (size_t)mrow * DM + c) =
            make_float2(co[nt][0] * inv0, co[nt][1] * inv0);
        *(float2*)(ob + (size_t)(mrow + 8) * DM + c) =
            make_float2(co[nt][2] * inv1, co[nt][3] * inv1);
    }
}

// ---------------- weight quant ----------------
__global__ void wmax(const float* __restrict__ w, float* __restrict__ sc,
                     int K, int M, size_t wz, size_t sz) {
    __shared__ float red[8][32];
    w += blockIdx.z * wz; sc += blockIdx.z * sz;
    int c = blockIdx.x * 32 + threadIdx.x;
    float mx = 0.f;
    for (int r = threadIdx.y; r < K; r += 8)
        mx = fmaxf(mx, fabsf(w[(size_t)r * M + c]));
    red[threadIdx.y][threadIdx.x] = mx;
    __syncthreads();
    if (threadIdx.y == 0) {
        #pragma unroll
        for (int i = 1; i < 8; i++) mx = fmaxf(mx, red[i][threadIdx.x]);
        sc[c] = mx * (1.f / 32256.f);
    }
}

__global__ void wquant(const float* __restrict__ w, const float* __restrict__ sc,
                       int8_t* __restrict__ oh, int8_t* __restrict__ ol,
                       int K, int M, size_t wz, size_t sz, size_t oz) {
    __shared__ float tb[32][33];
    w += blockIdx.z * wz; sc += blockIdx.z * sz;
    oh += blockIdx.z * oz; ol += blockIdx.z * oz;
    int c0 = blockIdx.x * 32, r0 = blockIdx.y * 32;
    int tx = threadIdx.x, ty = threadIdx.y;
    #pragma unroll
    for (int i = 0; i < 32; i += 8)
        tb[ty + i][tx] = w[(size_t)(r0 + ty + i) * M + c0 + tx];
    __syncthreads();
    #pragma unroll
    for (int i = 0; i < 32; i += 8) {
        int c = c0 + ty + i;
        float s = sc[c];
        float inv = s > 0.f ? 1.f / s : 0.f;
        int q = __float2int_rn(tb[tx][ty + i] * inv);
        int8_t hi, lo;
        qsplit(q, hi, lo);
        size_t o = (size_t)c * K + r0 + tx;
        oh[o] = hi; ol[o] = lo;
    }
}

// ---------------- activation row quant ----------------
__global__ __launch_bounds__(256) void rowquant(const float* __restrict__ x,
                                                int8_t* __restrict__ oh,
                                                int8_t* __restrict__ ol,
                                                float* __restrict__ sa, int W) {
    __shared__ float red[8];
    int row = blockIdx.x, t = threadIdx.x;
    const float* xr = x + (size_t)row * W;
    int n = W >> 8;
    float v[8];
    float mx = 0.f;
    for (int i = 0; i < n; i++) { v[i] = xr[t + i * 256]; mx = fmaxf(mx, fabsf(v[i])); }
    #pragma unroll
    for (int off = 16; off; off >>= 1) mx = fmaxf(mx, __shfl_xor_sync(0xffffffffu, mx, off));
    if ((t & 31) == 0) red[t >> 5] = mx;
    __syncthreads();
    mx = red[0];
    #pragma unroll
    for (int i = 1; i < 8; i++) mx = fmaxf(mx, red[i]);
    float inv = mx > 0.f ? 32256.f / mx : 0.f;
    if (t == 0) sa[row] = mx * (1.f / 32256.f);
    for (int i = 0; i < n; i++) {
        int q = __float2int_rn(v[i] * inv);
        int8_t hi, lo;
        qsplit(q, hi, lo);
        size_t o = (size_t)row * W + t + i * 256;
        oh[o] = hi; ol[o] = lo;
    }
}

// ---------------- layernorm fused with row quant ----------------
__global__ __launch_bounds__(256) void ln_quant(const float* __restrict__ x,
                                                const float* __restrict__ w,
                                                const float* __restrict__ b,
                                                int8_t* __restrict__ oh,
                                                int8_t* __restrict__ ol,
                                                float* __restrict__ sa) {
    __shared__ float sred[24];
    int row = blockIdx.x, t = threadIdx.x;
    const float* xr = x + (size_t)row * DM;
    float2 v = *(const float2*)(xr + 2 * t);
    float s = v.x + v.y;
    #pragma unroll
    for (int off = 16; off; off >>= 1) s += __shfl_xor_sync(0xffffffffu, s, off);
    if ((t & 31) == 0) sred[t >> 5] = s;
    __syncthreads();
    float tot = 0.f;
    #pragma unroll
    for (int i = 0; i < 8; i++) tot += sred[i];
    float mu = tot * (1.0f / DM);
    float d0 = v.x - mu, d1 = v.y - mu;
    float s2 = d0 * d0 + d1 * d1;
    #pragma unroll
    for (int off = 16; off; off >>= 1) s2 += __shfl_xor_sync(0xffffffffu, s2, off);
    if ((t & 31) == 0) sred[8 + (t >> 5)] = s2;
    __syncthreads();
    float tot2 = 0.f;
    #pragma unroll
    for (int i = 0; i < 8; i++) tot2 += sred[8 + i];
    float rstd = rsqrtf(tot2 * (1.0f / DM) + 1e-5f);
    float y0 = d0 * rstd * w[2 * t]     + b[2 * t];
    float y1 = d1 * rstd * w[2 * t + 1] + b[2 * t + 1];
    float mx = fmaxf(fabsf(y0), fabsf(y1));
    #pragma unroll
    for (int off = 16; off; off >>= 1) mx = fmaxf(mx, __shfl_xor_sync(0xffffffffu, mx, off));
    if ((t & 31) == 0) sred[16 + (t >> 5)] = mx;
    __syncthreads();
    mx = sred[16];
    #pragma unroll
    for (int i = 1; i < 8; i++) mx = fmaxf(mx, sred[16 + i]);
    float inv = mx > 0.f ? 32256.f / mx : 0.f;
    if (t == 0) sa[row] = mx * (1.f / 32256.f);
    int q0 = __float2int_rn(y0 * inv), q1 = __float2int_rn(y1 * inv);
    int8_t h0, l0, h1, l1;
    qsplit(q0, h0, l0);
    qsplit(q1, h1, l1);
    ((uint16_t*)oh)[row * 256 + t] = (uint16_t)((uint8_t)h0 | ((uint32_t)(uint8_t)h1 << 8));
    ((uint16_t*)ol)[row * 256 + t] = (uint16_t)((uint8_t)l0 | ((uint32_t)(uint8_t)l1 << 8));
}

// ---------------- misc ----------------
__global__ __launch_bounds__(256) void biaspack_kernel(const float* __restrict__ bq,
                                                       const float* __restrict__ bk,
                                                       const float* __restrict__ bv,
                                                       float* __restrict__ dst) {
    int idx = blockIdx.x * 256 + threadIdx.x;
    if (idx >= NL * QKVW) return;
    int l = idx / QKVW, j = idx % QKVW;
    float v;
    if (j < 512)       v = bq[l * 512 + j];
    else if (j < 1024) v = bk[l * 512 + j - 512];
    else               v = bv[l * 512 + j - 1024];
    dst[idx] = v;
}

__global__ __launch_bounds__(256) void embed_kernel(const int* __restrict__ ids,
                                                    const float* __restrict__ emb,
                                                    float* __restrict__ x) {
    int idx = blockIdx.x * 256 + threadIdx.x;
    if (idx >= NTOK * DM) return;
    int row = idx >> 9, d = idx & 511, s = row & (SQ - 1);
    int tok = ids[row];
    int i2 = d & ~1;
    float div = expf(-(float)i2 * (9.210340371976184f / 512.0f));
    float ang = (float)s * div;
    float pe = (d & 1) ? cosf(ang) : sinf(ang);
    x[idx] = emb[(size_t)tok * DM + d] + pe;
}

// ---------------- host ----------------
static void run_gemm(const int8_t* Ah, const int8_t* Al,
                     const int8_t* Bh, const int8_t* Bl,
                     const float* sa, const float* sbv, const float* bias,
                     const float* R, float* C, int K, int M, int mode) {
    gemm_i8<<<dim3(M / 128, NTOK / 128), 256, QSMEM>>>(
        Ah, Al, Bh, Bl, sa, sbv, bias, R, C, K, M, mode);
}

extern "C" void kernel_launch(void* const* d_in, const int* in_sizes, int n_in,
                              void* d_out, int out_size) {
    (void)in_sizes; (void)n_in; (void)out_size;
    const int*   ids  = (const int*)  d_in[0];
    const float* emb  = (const float*)d_in[1];
    const float* wq   = (const float*)d_in[2];
    const float* bq   = (const float*)d_in[3];
    const float* wk   = (const float*)d_in[4];
    const float* bk   = (const float*)d_in[5];
    const float* wv   = (const float*)d_in[6];
    const float* bv   = (const float*)d_in[7];
    const float* wo   = (const float*)d_in[8];
    const float* bo   = (const float*)d_in[9];
    const float* ln1w = (const float*)d_in[10];
    const float* ln1b = (const float*)d_in[11];
    const float* ln2w = (const float*)d_in[12];
    const float* ln2b = (const float*)d_in[13];
    const float* w1   = (const float*)d_in[14];
    const float* b1   = (const float*)d_in[15];
    const float* w2   = (const float*)d_in[16];
    const float* b2   = (const float*)d_in[17];
    const float* outw = (const float*)d_in[18];
    const float* outb = (const float*)d_in[19];

    float *x, *h, *qkv, *ff, *sa, *bqkv;
    float *sbqkv, *sbo, *sb1, *sb2, *sow;
    int8_t *ah8, *al8, *wqkvh, *wqkvl, *woh, *wol, *w1h, *w1l, *w2h, *w2l, *owh, *owl;
    cudaGetSymbolAddress((void**)&x,   g_x);
    cudaGetSymbolAddress((void**)&h,   g_h);
    cudaGetSymbolAddress((void**)&qkv, g_qkv);
    cudaGetSymbolAddress((void**)&ff,  g_ff);
    cudaGetSymbolAddress((void**)&sa,  g_sa);
    cudaGetSymbolAddress((void**)&ah8, g_ah8);
    cudaGetSymbolAddress((void**)&al8, g_al8);
    cudaGetSymbolAddress((void**)&bqkv, g_bqkv);
    cudaGetSymbolAddress((void**)&sbqkv, g_sbqkv);
    cudaGetSymbolAddress((void**)&sbo, g_sbo);
    cudaGetSymbolAddress((void**)&sb1, g_sb1);
    cudaGetSymbolAddress((void**)&sb2, g_sb2);
    cudaGetSymbolAddress((void**)&sow, g_sow);
    cudaGetSymbolAddress((void**)&wqkvh, g_wqkv_h); cudaGetSymbolAddress((void**)&wqkvl, g_wqkv_l);
    cudaGetSymbolAddress((void**)&woh, g_wo_h);     cudaGetSymbolAddress((void**)&wol, g_wo_l);
    cudaGetSymbolAddress((void**)&w1h, g_w1_h);     cudaGetSymbolAddress((void**)&w1l, g_w1_l);
    cudaGetSymbolAddress((void**)&w2h, g_w2_h);     cudaGetSymbolAddress((void**)&w2l, g_w2_l);
    cudaGetSymbolAddress((void**)&owh, g_ow_h);     cudaGetSymbolAddress((void**)&owl, g_ow_l);

    cudaFuncSetAttribute(gemm_i8, cudaFuncAttributeMaxDynamicSharedMemorySize, QSMEM);
    cudaFuncSetAttribute(attn_mma, cudaFuncAttributeMaxDynamicSharedMemorySize, ATTN_SMEM);

    dim3 wb(32, 8);
    size_t DD = (size_t)DM * DM, DF = (size_t)DM * DFF;
    wmax<<<dim3(16, 1, NL), wb>>>(wq, sbqkv,        DM, DM, DD, QKVW);
    wmax<<<dim3(16, 1, NL), wb>>>(wk, sbqkv + 512,  DM, DM, DD, QKVW);
    wmax<<<dim3(16, 1, NL), wb>>>(wv, sbqkv + 1024, DM, DM, DD, QKVW);
    wmax<<<dim3(16, 1, NL), wb>>>(wo, sbo, DM, DM, DD, DM);
    wmax<<<dim3(64, 1, NL), wb>>>(w1, sb1, DM, DFF, DF, DFF);
    wmax<<<dim3(16, 1, NL), wb>>>(w2, sb2, DFF, DM, DF, DM);
    wmax<<<dim3(32, 1, 1),  wb>>>(outw, sow, DM, NV, 0, 0);
    size_t QZ = (size_t)QKVW * DM;
    wquant<<<dim3(16, 16, NL), wb>>>(wq, sbqkv,        wqkvh,             wqkvl,             DM, DM, DD, QKVW, QZ);
    wquant<<<dim3(16, 16, NL), wb>>>(wk, sbqkv + 512,  wqkvh + 512 * DM,  wqkvl + 512 * DM,  DM, DM, DD, QKVW, QZ);
    wquant<<<dim3(16, 16, NL), wb>>>(wv, sbqkv + 1024, wqkvh + 1024 * DM, wqkvl + 1024 * DM, DM, DM, DD, QKVW, QZ);
    wquant<<<dim3(16, 16, NL), wb>>>(wo, sbo, woh, wol, DM, DM, DD, DM, DD);
    wquant<<<dim3(64, 16, NL), wb>>>(w1, sb1, w1h, w1l, DM, DFF, DF, DFF, DF);
    wquant<<<dim3(16, 64, NL), wb>>>(w2, sb2, w2h, w2l, DFF, DM, DF, DM, DF);
    wquant<<<dim3(32, 16, 1),  wb>>>(outw, sow, owh, owl, DM, NV, 0, 0, 0);
    biaspack_kernel<<<(NL * QKVW + 255) / 256, 256>>>(bq, bk, bv, bqkv);

    embed_kernel<<<(NTOK * DM) / 256, 256>>>(ids, emb, x);

    for (int l = 0; l < NL; l++) {
        size_t offD = (size_t)l * DM;
        size_t offF = (size_t)l * DFF;

        ln_quant<<<NTOK, 256>>>(x, ln1w + offD, ln1b + offD, ah8, al8, sa);
        run_gemm(ah8, al8, wqkvh + l * QZ, wqkvl + l * QZ, sa, sbqkv + (size_t)l * QKVW,
                 bqkv + (size_t)l * QKVW, nullptr, qkv, DM, QKVW, 2 /*tf32 round*/);
        attn_mma<<<dim3(SQ / 64, NB * NH), 128, ATTN_SMEM>>>(qkv, h);
        rowquant<<<NTOK, 256>>>(h, ah8, al8, sa, DM);
        run_gemm(ah8, al8, woh + l * DD, wol + l * DD, sa, sbo + offD,
                 bo + offD, nullptr, x, DM, DM, 0);
        ln_quant<<<NTOK, 256>>>(x, ln2w + offD, ln2b + offD, ah8, al8, sa);
        run_gemm(ah8, al8, w1h + l * DF, w1l + l * DF, sa, sb1 + offF,
                 b1 + offF, nullptr, ff, DM, DFF, 1 /*relu*/);
        rowquant<<<NTOK, 256>>>(ff, ah8, al8, sa, DFF);
        run_gemm(ah8, al8, w2h + l * DF, w2l + l * DF, sa, sb2 + offD,
                 b2 + offD, x /*residual*/, x, DFF, DM, 0);
    }

    rowquant<<<NTOK, 256>>>(x, ah8, al8, sa, DM);
    run_gemm(ah8, al8, owh, owl, sa, sow, outb, nullptr, (float*)d_out, DM, NV, 0);
}

// round 8
// speedup vs baseline: 2.2387x; 2.2387x over previous
#include <cuda_runtime.h>
#include <math.h>
#include <stdint.h>

#define NB 2
#define SQ 2048
#define NTOK 4096
#define DM 512
#define NH 8
#define DK 64
#define NL 6
#define DFF 2048
#define NV 1024
#define QKVW 1536

// ---------------- scratch ----------------
__device__ float g_x   [NTOK * DM];
__device__ float g_h   [NTOK * DM];
__device__ float g_qkv [NTOK * QKVW];
__device__ float g_ff  [NTOK * DFF];
__device__ float g_vt  [16 * 64 * SQ];          // per (b,h): V transposed [d][s]
__device__ float g_wqkvT[NL * QKVW * DM];
__device__ float g_woT  [NL * DM * DM];
__device__ float g_w1T  [NL * DFF * DM];
__device__ float g_w2T  [NL * DM * DFF];
__device__ float g_outwT[NV * DM];
__device__ float g_bqkv [NL * QKVW];

// ---------------- helpers ----------------
__device__ __forceinline__ uint32_t f2tf(float f) {
    uint32_t r;
    asm("cvt.rna.tf32.f32 %0, %1;" : "=r"(r) : "f"(f));
    return r;
}
__device__ __forceinline__ float tfround(float f) { return __uint_as_float(f2tf(f)); }
__device__ __forceinline__ void mma8(float* c, const uint32_t* a, const uint32_t* b) {
    asm volatile(
        "mma.sync.aligned.m16n8k8.row.col.f32.tf32.tf32.f32 "
        "{%0,%1,%2,%3}, {%4,%5,%6,%7}, {%8,%9}, {%0,%1,%2,%3};\n"
        : "+f"(c[0]), "+f"(c[1]), "+f"(c[2]), "+f"(c[3])
        : "r"(a[0]), "r"(a[1]), "r"(a[2]), "r"(a[3]), "r"(b[0]), "r"(b[1]));
}
__device__ __forceinline__ void cpa16(uint32_t dst, const void* src) {
    asm volatile("cp.async.cg.shared.global [%0], [%1], 16;" :: "r"(dst), "l"(src));
}
#define CP_COMMIT() asm volatile("cp.async.commit_group;" ::: "memory")
#define CP_WAIT(n)  asm volatile("cp.async.wait_group %0;" :: "n"(n) : "memory")
__device__ __forceinline__ uint32_t smem_u32(const void* p) {
    uint32_t a;
    asm("{ .reg .u64 t; cvta.to.shared.u64 t, %1; cvt.u32.u64 %0, t; }" : "=r"(a) : "l"(p));
    return a;
}

// ---------------- tf32 mma GEMM (R3-proven) + mode epilogue ----------------
#define GP 36
#define GSTAGE 9216
#define GEMM_SMEM (2 * GSTAGE * 4)

__global__ __launch_bounds__(256) void mma_gemm(const float* __restrict__ A,
                                                const float* __restrict__ Wt,
                                                const float* __restrict__ bias,
                                                const float* __restrict__ R,
                                                float* __restrict__ C,
                                                int K, int M, int mode) {
    extern __shared__ uint32_t sm[];
    int t = threadIdx.x, lane = t & 31, wid = t >> 5;
    int wm = wid & 1, wn = wid >> 1;
    int gr = lane >> 2, lc = lane & 3;
    int row0 = blockIdx.y * 128, col0 = blockIdx.x * 128;
    const int NC = K >> 5;

    float acc[4][4][4];
    #pragma unroll
    for (int i = 0; i < 4; i++)
        #pragma unroll
        for (int j = 0; j < 4; j++)
            #pragma unroll
            for (int k = 0; k < 4; k++) acc[i][j][k] = 0.f;

    float4 ra[4], rb[4];
    #pragma unroll
    for (int i = 0; i < 4; i++) {
        int idx = i * 256 + t, r = idx >> 3, c = (idx & 7) << 2;
        ra[i] = *(const float4*)(A  + (size_t)(row0 + r) * K + c);
        rb[i] = *(const float4*)(Wt + (size_t)(col0 + r) * K + c);
    }
    {
        uint32_t* Ab = sm;
        uint32_t* Bb = sm + 4608;
        #pragma unroll
        for (int i = 0; i < 4; i++) {
            int idx = i * 256 + t, r = idx >> 3, c = (idx & 7) << 2, off = r * GP + c;
            *(uint4*)(Ab + off) = make_uint4(f2tf(ra[i].x), f2tf(ra[i].y), f2tf(ra[i].z), f2tf(ra[i].w));
            *(uint4*)(Bb + off) = make_uint4(f2tf(rb[i].x), f2tf(rb[i].y), f2tf(rb[i].z), f2tf(rb[i].w));
        }
    }
    __syncthreads();

    for (int cch = 0; cch < NC; cch++) {
        if (cch + 1 < NC) {
            int k0 = (cch + 1) << 5;
            #pragma unroll
            for (int i = 0; i < 4; i++) {
                int idx = i * 256 + t, r = idx >> 3, c = (idx & 7) << 2;
                ra[i] = *(const float4*)(A  + (size_t)(row0 + r) * K + k0 + c);
                rb[i] = *(const float4*)(Wt + (size_t)(col0 + r) * K + k0 + c);
            }
        }
        {
            const uint32_t* Ab = sm + (cch & 1) * GSTAGE;
            const uint32_t* Bb = Ab + 4608;
            const uint32_t* Abase = Ab + (wm * 64 + gr) * GP + lc;
            const uint32_t* Bbase = Bb + (wn * 32 + gr) * GP + lc;
            #pragma unroll
            for (int ks = 0; ks < 4; ks++) {
                uint32_t a[4][4], b[4][2];
                #pragma unroll
                for (int mt = 0; mt < 4; mt++) {
                    const uint32_t* p = Abase + mt * 16 * GP + ks * 8;
                    a[mt][0] = p[0]; a[mt][1] = p[8 * GP]; a[mt][2] = p[4]; a[mt][3] = p[8 * GP + 4];
                }
                #pragma unroll
                for (int nt = 0; nt < 4; nt++) {
                    const uint32_t* p = Bbase + nt * 8 * GP + ks * 8;
                    b[nt][0] = p[0]; b[nt][1] = p[4];
                }
                #pragma unroll
                for (int mt = 0; mt < 4; mt++)
                    #pragma unroll
                    for (int nt = 0; nt < 4; nt++)
                        mma8(acc[mt][nt], a[mt], b[nt]);
            }
        }
        if (cch + 1 < NC) {
            __syncthreads();
            uint32_t* Ab = sm + ((cch + 1) & 1) * GSTAGE;
            uint32_t* Bb = Ab + 4608;
            #pragma unroll
            for (int i = 0; i < 4; i++) {
                int idx = i * 256 + t, r = idx >> 3, c = (idx & 7) << 2, off = r * GP + c;
                *(uint4*)(Ab + off) = make_uint4(f2tf(ra[i].x), f2tf(ra[i].y), f2tf(ra[i].z), f2tf(ra[i].w));
                *(uint4*)(Bb + off) = make_uint4(f2tf(rb[i].x), f2tf(rb[i].y), f2tf(rb[i].z), f2tf(rb[i].w));
            }
            __syncthreads();
        }
    }

    #pragma unroll
    for (int mt = 0; mt < 4; mt++) {
        int r = row0 + wm * 64 + mt * 16 + gr;
        #pragma unroll
        for (int nt = 0; nt < 4; nt++) {
            int c = col0 + wn * 32 + nt * 8 + lc * 2;
            float b0 = bias[c], b1 = bias[c + 1];
            #pragma unroll
            for (int h2 = 0; h2 < 2; h2++) {
                size_t off = (size_t)(r + h2 * 8) * M + c;
                float v0 = acc[mt][nt][h2 * 2 + 0] + b0;
                float v1 = acc[mt][nt][h2 * 2 + 1] + b1;
                if (R) { float2 rv = *(const float2*)(R + off); v0 += rv.x; v1 += rv.y; }
                if (mode == 1) { v0 = fmaxf(v0, 0.f); v1 = fmaxf(v1, 0.f); }
                if (mode == 2) { v0 = tfround(v0); v1 = tfround(v1); }
                *(float2*)(C + off) = make_float2(v0, v1);
            }
        }
    }
}

// ---------------- flash attention v2: cp.async pipelined, R3-identical numerics ----------------
#define AP 68
#define OQ 0
#define OK0 4352
#define OV0 13056
#define OPS 21760
#define OST 26112
#define ATTN_SMEM ((OST + 192) * 4)

__global__ __launch_bounds__(128) void attn_mma(const float* __restrict__ qkv,
                                                const float* __restrict__ vt,
                                                float* __restrict__ out) {
    extern __shared__ uint32_t smu[];
    uint32_t sb = smem_u32(smu);
    int qt = blockIdx.x, bh = blockIdx.y, bb = bh >> 3, hh = bh & 7;
    int t = threadIdx.x, lane = t & 31, wid = t >> 5;
    int gr = lane >> 2, lc = lane & 3;
    int mrow = wid * 16 + gr;
    const size_t base = (size_t)bb * SQ * QKVW + hh * DK;
    const float* qb = qkv + base + (size_t)qt * 64 * QKVW;
    const float* vbase = vt + (size_t)bh * 64 * SQ;

    float* sm_m  = (float*)(smu + OST);
    float* sm_l  = sm_m + 64;
    float* sm_rs = sm_m + 128;
    uint32_t* Qs = smu + OQ;
    float*    Ps = (float*)(smu + OPS);

    // prologue: Q + K0 + V0 in one group
    #pragma unroll
    for (int i = 0; i < 8; i++) {
        int f = i * 128 + t, r = f >> 4, d4 = (f & 15) << 2;
        cpa16(sb + (OQ + r * AP + d4) * 4, qb + (size_t)r * QKVW + d4);
    }
    {
        const float* kb = qkv + base + 512;
        #pragma unroll
        for (int i = 0; i < 8; i++) {
            int f = i * 128 + t, r = f >> 4, d4 = (f & 15) << 2;
            cpa16(sb + (OK0 + r * AP + d4) * 4, kb + (size_t)r * QKVW + d4);
        }
        #pragma unroll
        for (int i = 0; i < 8; i++) {
            int f = i * 128 + t, d = f >> 4, k4 = (f & 15) << 2;
            cpa16(sb + (OV0 + d * AP + k4) * 4, vbase + (size_t)d * SQ + k4);
        }
    }
    CP_COMMIT();

    if (lane < 16) { sm_m[wid * 16 + lane] = -1e30f; sm_l[wid * 16 + lane] = 0.f; }

    float co[8][4];
    #pragma unroll
    for (int i = 0; i < 8; i++)
        #pragma unroll
        for (int j = 0; j < 4; j++) co[i][j] = 0.f;

    for (int kt = 0; kt <= qt; kt++) {
        int cur = kt & 1;
        __syncthreads();   // prior iteration's mma reads of the other buffers are done
        if (kt < qt) {
            int nb = cur ^ 1;
            const float* kb = qkv + base + 512 + (size_t)(kt + 1) * 64 * QKVW;
            #pragma unroll
            for (int i = 0; i < 8; i++) {
                int f = i * 128 + t, r = f >> 4, d4 = (f & 15) << 2;
                cpa16(sb + (OK0 + nb * 4352 + r * AP + d4) * 4, kb + (size_t)r * QKVW + d4);
            }
            #pragma unroll
            for (int i = 0; i < 8; i++) {
                int f = i * 128 + t, d = f >> 4, k4 = (f & 15) << 2;
                cpa16(sb + (OV0 + nb * 4352 + d * AP + k4) * 4,
                      vbase + (size_t)d * SQ + (kt + 1) * 64 + k4);
            }
            CP_COMMIT();
            CP_WAIT(1);
        } else {
            CP_WAIT(0);
        }
        __syncthreads();   // staged data visible to all warps

        const uint32_t* Kb = smu + OK0 + cur * 4352;
        const uint32_t* Vb = smu + OV0 + cur * 4352;

        // ---- S = Q K^T ----
        float cs[8][4];
        #pragma unroll
        for (int i = 0; i < 8; i++)
            #pragma unroll
            for (int j = 0; j < 4; j++) cs[i][j] = 0.f;
        {
            const uint32_t* Abase = Qs + mrow * AP + lc;
            const uint32_t* Bbase = Kb + gr * AP + lc;
            #pragma unroll
            for (int ks = 0; ks < 8; ks++) {
                uint32_t a[4];
                const uint32_t* p = Abase + ks * 8;
                a[0] = p[0]; a[1] = p[8 * AP]; a[2] = p[4]; a[3] = p[8 * AP + 4];
                #pragma unroll
                for (int nt = 0; nt < 8; nt++) {
                    const uint32_t* q2 = Bbase + nt * 8 * AP + ks * 8;
                    uint32_t b[2] = {q2[0], q2[4]};
                    mma8(cs[nt], a, b);
                }
            }
        }
        #pragma unroll
        for (int nt = 0; nt < 8; nt++) {
            int c = nt * 8 + lc * 2;
            *(float2*)(Ps + mrow * AP + c)       = make_float2(cs[nt][0], cs[nt][1]);
            *(float2*)(Ps + (mrow + 8) * AP + c) = make_float2(cs[nt][2], cs[nt][3]);
        }
        __syncwarp();   // Ps rows of this warp -> softmax threads of same warp

        // ---- online softmax (thread pair per row; all intra-warp) ----
        {
            int r = t >> 1, half = t & 1;
            int qrow = qt * 64 + r;
            int kbase0 = kt * 64 + half * 32;
            float* rowp = Ps + r * AP + half * 32;
            float vals[32];
            float mx = -1e30f;
            bool edge = (kt == qt);
            #pragma unroll
            for (int j = 0; j < 32; j += 4) {
                float4 v4 = *(const float4*)(rowp + j);
                float w0 = v4.x * 0.125f, w1 = v4.y * 0.125f;
                float w2 = v4.z * 0.125f, w3 = v4.w * 0.125f;
                if (edge) {
                    if (kbase0 + j + 0 > qrow) w0 = -1e30f;
                    if (kbase0 + j + 1 > qrow) w1 = -1e30f;
                    if (kbase0 + j + 2 > qrow) w2 = -1e30f;
                    if (kbase0 + j + 3 > qrow) w3 = -1e30f;
                }
                vals[j] = w0; vals[j+1] = w1; vals[j+2] = w2; vals[j+3] = w3;
                mx = fmaxf(mx, fmaxf(fmaxf(w0, w1), fmaxf(w2, w3)));
            }
            mx = fmaxf(mx, __shfl_xor_sync(0xffffffffu, mx, 1));
            float mo = sm_m[r];
            float mn = fmaxf(mo, mx);
            float rs = __expf(mo - mn);
            float ssum = 0.f;
            #pragma unroll
            for (int j = 0; j < 32; j += 4) {
                float p0 = __expf(vals[j]   - mn), p1 = __expf(vals[j+1] - mn);
                float p2 = __expf(vals[j+2] - mn), p3 = __expf(vals[j+3] - mn);
                ssum += (p0 + p1) + (p2 + p3);
                *(uint4*)(rowp + j) = make_uint4(f2tf(p0), f2tf(p1), f2tf(p2), f2tf(p3));
            }
            ssum += __shfl_xor_sync(0xffffffffu, ssum, 1);
            if (!half) { sm_l[r] = sm_l[r] * rs + ssum; sm_m[r] = mn; sm_rs[r] = rs; }
        }
        __syncwarp();

        // ---- O = O*rs + P V ----
        {
            float rs0 = sm_rs[mrow], rs1 = sm_rs[mrow + 8];
            #pragma unroll
            for (int nt = 0; nt < 8; nt++) {
                co[nt][0] *= rs0; co[nt][1] *= rs0;
                co[nt][2] *= rs1; co[nt][3] *= rs1;
            }
            const uint32_t* Pb = (const uint32_t*)Ps + mrow * AP + lc;
            const uint32_t* Bbase = Vb + gr * AP + lc;
            #pragma unroll
            for (int ks = 0; ks < 8; ks++) {
                uint32_t a[4];
                const uint32_t* p = Pb + ks * 8;
                a[0] = p[0]; a[1] = p[8 * AP]; a[2] = p[4]; a[3] = p[8 * AP + 4];
                #pragma unroll
                for (int nt = 0; nt < 8; nt++) {
                    const uint32_t* q2 = Bbase + nt * 8 * AP + ks * 8;
                    uint32_t b[2] = {q2[0], q2[4]};
                    mma8(co[nt], a, b);
                }
            }
        }
    }

    float inv0 = 1.f / sm_l[mrow], inv1 = 1.f / sm_l[mrow + 8];
    float* ob = out + ((size_t)bb * SQ + (size_t)qt * 64) * DM + hh * DK;
    #pragma unroll
    for (int nt = 0; nt < 8; nt++) {
        int c = nt * 8 + lc * 2;
        *(float2*)(ob + (size_t)mrow * DM + c) =
            make_float2(co[nt][0] * inv0, co[nt][1] * inv0);
        *(float2*)(ob + (size_t)(mrow + 8) * DM + c) =
            make_float2(co[nt][2] * inv1, co[nt][3] * inv1);
    }
}

// ---------------- V pre-transpose: qkv v-section -> vt[bh][d][s] ----------------
__global__ __launch_bounds__(256) void vtrans(const float* __restrict__ qkv,
                                              float* __restrict__ vt) {
    __shared__ float tb[32][33];
    int bhid = blockIdx.z, bb = bhid >> 3, hh = bhid & 7;
    int s0 = blockIdx.x * 32, d0 = blockIdx.y * 32;
    const float* in = qkv + (size_t)bb * SQ * QKVW + 1024 + hh * 64;
    float* outp = vt + (size_t)bhid * 64 * SQ;
    int tx = threadIdx.x, ty = threadIdx.y;
    #pragma unroll
    for (int i = 0; i < 32; i += 8)
        tb[ty + i][tx] = in[(size_t)(s0 + ty + i) * QKVW + d0 + tx];
    __syncthreads();
    #pragma unroll
    for (int i = 0; i < 32; i += 8)
        outp[(size_t)(d0 + ty + i) * SQ + s0 + tx] = tb[tx][ty + i];
}

// ---------------- weight transpose ----------------
__global__ __launch_bounds__(256) void transpose_k(const float* __restrict__ in,
                                                   float* __restrict__ out,
                                                   int R, int C,
                                                   size_t in_z, size_t out_z) {
    __shared__ float tbuf[32][33];
    in  += blockIdx.z * in_z;
    out += blockIdx.z * out_z;
    int c0 = blockIdx.x * 32, r0 = blockIdx.y * 32;
    #pragma unroll
    for (int i = 0; i < 32; i += 8)
        tbuf[threadIdx.y + i][threadIdx.x] = in[(size_t)(r0 + threadIdx.y + i) * C + c0 + threadIdx.x];
    __syncthreads();
    #pragma unroll
    for (int i = 0; i < 32; i += 8)
        out[(size_t)(c0 + threadIdx.y + i) * R + r0 + threadIdx.x] = tbuf[threadIdx.x][threadIdx.y + i];
}

__global__ __launch_bounds__(256) void biaspack_kernel(const float* __restrict__ bq,
                                                       const float* __restrict__ bk,
                                                       const float* __restrict__ bv,
                                                       float* __restrict__ dst) {
    int idx = blockIdx.x * 256 + threadIdx.x;
    if (idx >= NL * QKVW) return;
    int l = idx / QKVW, j = idx % QKVW;
    float v;
    if (j < 512)       v = bq[l * 512 + j];
    else if (j < 1024) v = bk[l * 512 + j - 512];
    else               v = bv[l * 512 + j - 1024];
    dst[idx] = v;
}

__global__ __launch_bounds__(256) void embed_kernel(const int* __restrict__ ids,
                                                    const float* __restrict__ emb,
                                                    float* __restrict__ x) {
    int idx = blockIdx.x * 256 + threadIdx.x;
    if (idx >= NTOK * DM) return;
    int row = idx >> 9, d = idx & 511, s = row & (SQ - 1);
    int tok = ids[row];
    int i2 = d & ~1;
    float div = expf(-(float)i2 * (9.210340371976184f / 512.0f));
    float ang = (float)s * div;
    float pe = (d & 1) ? cosf(ang) : sinf(ang);
    x[idx] = emb[(size_t)tok * DM + d] + pe;
}

__global__ __launch_bounds__(256) void ln_kernel(const float* __restrict__ x,
                                                 const float* __restrict__ w,
                                                 const float* __restrict__ bias,
                                                 float* __restrict__ y) {
    __shared__ float sred[16];
    int row = blockIdx.x;
    int t = threadIdx.x;
    const float* xr = x + (size_t)row * DM;
    float v0 = xr[t];
    float v1 = xr[t + 256];
    float s = v0 + v1;
    #pragma unroll
    for (int off = 16; off; off >>= 1) s += __shfl_xor_sync(0xffffffffu, s, off);
    if ((t & 31) == 0) sred[t >> 5] = s;
    __syncthreads();
    float tot = 0.f;
    #pragma unroll
    for (int i = 0; i < 8; i++) tot += sred[i];
    float mu = tot * (1.0f / DM);
    float d0 = v0 - mu, d1 = v1 - mu;
    float s2 = d0 * d0 + d1 * d1;
    #pragma unroll
    for (int off = 16; off; off >>= 1) s2 += __shfl_xor_sync(0xffffffffu, s2, off);
    if ((t & 31) == 0) sred[8 + (t >> 5)] = s2;
    __syncthreads();
    float tot2 = 0.f;
    #pragma unroll
    for (int i = 0; i < 8; i++) tot2 += sred[8 + i];
    float var = tot2 * (1.0f / DM);
    float rstd = rsqrtf(var + 1e-5f);
    float* yr = y + (size_t)row * DM;
    yr[t]       = d0 * rstd * w[t]       + bias[t];
    yr[t + 256] = d1 * rstd * w[t + 256] + bias[t + 256];
}

// ---------------- host ----------------
static void run_gemm(const float* A, const float* Wt, const float* bias, const float* R,
                     float* C, int K, int M, int mode) {
    mma_gemm<<<dim3(M / 128, NTOK / 128), 256, GEMM_SMEM>>>(A, Wt, bias, R, C, K, M, mode);
}

extern "C" void kernel_launch(void* const* d_in, const int* in_sizes, int n_in,
                              void* d_out, int out_size) {
    (void)in_sizes; (void)n_in; (void)out_size;
    const int*   ids  = (const int*)  d_in[0];
    const float* emb  = (const float*)d_in[1];
    const float* wq   = (const float*)d_in[2];
    const float* bq   = (const float*)d_in[3];
    const float* wk   = (const float*)d_in[4];
    const float* bk   = (const float*)d_in[5];
    const float* wv   = (const float*)d_in[6];
    const float* bv   = (const float*)d_in[7];
    const float* wo   = (const float*)d_in[8];
    const float* bo   = (const float*)d_in[9];
    const float* ln1w = (const float*)d_in[10];
    const float* ln1b = (const float*)d_in[11];
    const float* ln2w = (const float*)d_in[12];
    const float* ln2b = (const float*)d_in[13];
    const float* w1   = (const float*)d_in[14];
    const float* b1   = (const float*)d_in[15];
    const float* w2   = (const float*)d_in[16];
    const float* b2   = (const float*)d_in[17];
    const float* outw = (const float*)d_in[18];
    const float* outb = (const float*)d_in[19];

    float *x, *h, *qkv, *ff, *vt, *wqkvT, *woT, *w1T, *w2T, *outwT, *bqkv;
    cudaGetSymbolAddress((void**)&x,     g_x);
    cudaGetSymbolAddress((void**)&h,     g_h);
    cudaGetSymbolAddress((void**)&qkv,   g_qkv);
    cudaGetSymbolAddress((void**)&ff,    g_ff);
    cudaGetSymbolAddress((void**)&vt,    g_vt);
    cudaGetSymbolAddress((void**)&wqkvT, g_wqkvT);
    cudaGetSymbolAddress((void**)&woT,   g_woT);
    cudaGetSymbolAddress((void**)&w1T,   g_w1T);
    cudaGetSymbolAddress((void**)&w2T,   g_w2T);
    cudaGetSymbolAddress((void**)&outwT, g_outwT);
    cudaGetSymbolAddress((void**)&bqkv,  g_bqkv);

    cudaFuncSetAttribute(mma_gemm, cudaFuncAttributeMaxDynamicSharedMemorySize, GEMM_SMEM);
    cudaFuncSetAttribute(attn_mma, cudaFuncAttributeMaxDynamicSharedMemorySize, ATTN_SMEM);

    dim3 tb(32, 8);
    transpose_k<<<dim3(16, 16, NL), tb>>>(wq, wqkvT + 0,       DM, DM, (size_t)DM*DM, (size_t)QKVW*DM);
    transpose_k<<<dim3(16, 16, NL), tb>>>(wk, wqkvT + DM*DM,   DM, DM, (size_t)DM*DM, (size_t)QKVW*DM);
    transpose_k<<<dim3(16, 16, NL), tb>>>(wv, wqkvT + 2*DM*DM, DM, DM, (size_t)DM*DM, (size_t)QKVW*DM);
    transpose_k<<<dim3(16, 16, NL), tb>>>(wo, woT,             DM, DM, (size_t)DM*DM, (size_t)DM*DM);
    transpose_k<<<dim3(DFF/32, 16, NL), tb>>>(w1, w1T, DM, DFF, (size_t)DM*DFF, (size_t)DM*DFF);
    transpose_k<<<dim3(16, DFF/32, NL), tb>>>(w2, w2T, DFF, DM, (size_t)DM*DFF, (size_t)DM*DFF);
    transpose_k<<<dim3(NV/32, 16, 1),   tb>>>(outw, outwT, DM, NV, 0, 0);
    biaspack_kernel<<<(NL * QKVW + 255) / 256, 256>>>(bq, bk, bv, bqkv);

    embed_kernel<<<(NTOK * DM) / 256, 256>>>(ids, emb, x);

    for (int l = 0; l < NL; l++) {
        size_t offD = (size_t)l * DM;
        size_t offF = (size_t)l * DFF;

        ln_kernel<<<NTOK, 256>>>(x, ln1w + offD, ln1b + offD, h);
        run_gemm(h, wqkvT + (size_t)l * QKVW * DM, bqkv + (size_t)l * QKVW, nullptr,
                 qkv, DM, QKVW, 2 /* tf32-round: same values R3 produced at staging */);
        vtrans<<<dim3(SQ / 32, 2, NB * NH), tb>>>(qkv, vt);
        attn_mma<<<dim3(SQ / 64, NB * NH), 128, ATTN_SMEM>>>(qkv, vt, h);
        run_gemm(h, woT + (size_t)l * DM * DM, bo + offD, nullptr, x, DM, DM, 0);
        ln_kernel<<<NTOK, 256>>>(x, ln2w + offD, ln2b + offD, h);
        run_gemm(h, w1T + (size_t)l * DM * DFF, b1 + offF, nullptr, ff, DM, DFF, 1);
        run_gemm(ff, w2T + (size_t)l * DM * DFF, b2 + offD, x /*residual*/, x, DFF, DM, 0);
    }

    run_gemm(x, outwT, outb, nullptr, (float*)d_out, DM, NV, 0);
}

// round 9
// speedup vs baseline: 2.3974x; 1.0709x over previous
#include <cuda_runtime.h>
#include <math.h>
#include <stdint.h>

#define NB 2
#define SQ 2048
#define NTOK 4096
#define DM 512
#define NH 8
#define DK 64
#define NL 6
#define DFF 2048
#define NV 1024
#define QKVW 1536

// ---------------- scratch ----------------
__device__ float g_x   [NTOK * DM];
__device__ float g_h   [NTOK * DM];
__device__ float g_qkv [NTOK * QKVW];
__device__ float g_ff  [NTOK * DFF];
__device__ float g_vt  [16 * 64 * SQ];          // per (b,h): V transposed [d][s]
__device__ float g_wqkvT[NL * QKVW * DM];
__device__ float g_woT  [NL * DM * DM];
__device__ float g_w1T  [NL * DFF * DM];
__device__ float g_w2T  [NL * DM * DFF];
__device__ float g_outwT[NV * DM];
__device__ float g_bqkv [NL * QKVW];

// ---------------- helpers ----------------
__device__ __forceinline__ uint32_t f2tf(float f) {
    uint32_t r;
    asm("cvt.rna.tf32.f32 %0, %1;" : "=r"(r) : "f"(f));
    return r;
}
__device__ __forceinline__ float tfround(float f) { return __uint_as_float(f2tf(f)); }
__device__ __forceinline__ void mma8(float* c, const uint32_t* a, const uint32_t* b) {
    asm volatile(
        "mma.sync.aligned.m16n8k8.row.col.f32.tf32.tf32.f32 "
        "{%0,%1,%2,%3}, {%4,%5,%6,%7}, {%8,%9}, {%0,%1,%2,%3};\n"
        : "+f"(c[0]), "+f"(c[1]), "+f"(c[2]), "+f"(c[3])
        : "r"(a[0]), "r"(a[1]), "r"(a[2]), "r"(a[3]), "r"(b[0]), "r"(b[1]));
}
__device__ __forceinline__ void cpa16(uint32_t dst, const void* src) {
    asm volatile("cp.async.cg.shared.global [%0], [%1], 16;" :: "r"(dst), "l"(src));
}
#define CP_COMMIT() asm volatile("cp.async.commit_group;" ::: "memory")
#define CP_WAIT(n)  asm volatile("cp.async.wait_group %0;" :: "n"(n) : "memory")
__device__ __forceinline__ uint32_t smem_u32(const void* p) {
    uint32_t a;
    asm("{ .reg .u64 t; cvta.to.shared.u64 t, %1; cvt.u32.u64 %0, t; }" : "=r"(a) : "l"(p));
    return a;
}

// ---------------- tf32 mma GEMM (R3-proven) + mode epilogue ----------------
#define GP 36
#define GSTAGE 9216
#define GEMM_SMEM (2 * GSTAGE * 4)

__global__ __launch_bounds__(256) void mma_gemm(const float* __restrict__ A,
                                                const float* __restrict__ Wt,
                                                const float* __restrict__ bias,
                                                const float* __restrict__ R,
                                                float* __restrict__ C,
                                                int K, int M, int mode) {
    extern __shared__ uint32_t sm[];
    int t = threadIdx.x, lane = t & 31, wid = t >> 5;
    int wm = wid & 1, wn = wid >> 1;
    int gr = lane >> 2, lc = lane & 3;
    int row0 = blockIdx.y * 128, col0 = blockIdx.x * 128;
    const int NC = K >> 5;

    float acc[4][4][4];
    #pragma unroll
    for (int i = 0; i < 4; i++)
        #pragma unroll
        for (int j = 0; j < 4; j++)
            #pragma unroll
            for (int k = 0; k < 4; k++) acc[i][j][k] = 0.f;

    float4 ra[4], rb[4];
    #pragma unroll
    for (int i = 0; i < 4; i++) {
        int idx = i * 256 + t, r = idx >> 3, c = (idx & 7) << 2;
        ra[i] = *(const float4*)(A  + (size_t)(row0 + r) * K + c);
        rb[i] = *(const float4*)(Wt + (size_t)(col0 + r) * K + c);
    }
    {
        uint32_t* Ab = sm;
        uint32_t* Bb = sm + 4608;
        #pragma unroll
        for (int i = 0; i < 4; i++) {
            int idx = i * 256 + t, r = idx >> 3, c = (idx & 7) << 2, off = r * GP + c;
            *(uint4*)(Ab + off) = make_uint4(f2tf(ra[i].x), f2tf(ra[i].y), f2tf(ra[i].z), f2tf(ra[i].w));
            *(uint4*)(Bb + off) = make_uint4(f2tf(rb[i].x), f2tf(rb[i].y), f2tf(rb[i].z), f2tf(rb[i].w));
        }
    }
    __syncthreads();

    for (int cch = 0; cch < NC; cch++) {
        if (cch + 1 < NC) {
            int k0 = (cch + 1) << 5;
            #pragma unroll
            for (int i = 0; i < 4; i++) {
                int idx = i * 256 + t, r = idx >> 3, c = (idx & 7) << 2;
                ra[i] = *(const float4*)(A  + (size_t)(row0 + r) * K + k0 + c);
                rb[i] = *(const float4*)(Wt + (size_t)(col0 + r) * K + k0 + c);
            }
        }
        {
            const uint32_t* Ab = sm + (cch & 1) * GSTAGE;
            const uint32_t* Bb = Ab + 4608;
            const uint32_t* Abase = Ab + (wm * 64 + gr) * GP + lc;
            const uint32_t* Bbase = Bb + (wn * 32 + gr) * GP + lc;
            #pragma unroll
            for (int ks = 0; ks < 4; ks++) {
                uint32_t a[4][4], b[4][2];
                #pragma unroll
                for (int mt = 0; mt < 4; mt++) {
                    const uint32_t* p = Abase + mt * 16 * GP + ks * 8;
                    a[mt][0] = p[0]; a[mt][1] = p[8 * GP]; a[mt][2] = p[4]; a[mt][3] = p[8 * GP + 4];
                }
                #pragma unroll
                for (int nt = 0; nt < 4; nt++) {
                    const uint32_t* p = Bbase + nt * 8 * GP + ks * 8;
                    b[nt][0] = p[0]; b[nt][1] = p[4];
                }
                #pragma unroll
                for (int mt = 0; mt < 4; mt++)
                    #pragma unroll
                    for (int nt = 0; nt < 4; nt++)
                        mma8(acc[mt][nt], a[mt], b[nt]);
            }
        }
        if (cch + 1 < NC) {
            __syncthreads();
            uint32_t* Ab = sm + ((cch + 1) & 1) * GSTAGE;
            uint32_t* Bb = Ab + 4608;
            #pragma unroll
            for (int i = 0; i < 4; i++) {
                int idx = i * 256 + t, r = idx >> 3, c = (idx & 7) << 2, off = r * GP + c;
                *(uint4*)(Ab + off) = make_uint4(f2tf(ra[i].x), f2tf(ra[i].y), f2tf(ra[i].z), f2tf(ra[i].w));
                *(uint4*)(Bb + off) = make_uint4(f2tf(rb[i].x), f2tf(rb[i].y), f2tf(rb[i].z), f2tf(rb[i].w));
            }
            __syncthreads();
        }
    }

    #pragma unroll
    for (int mt = 0; mt < 4; mt++) {
        int r = row0 + wm * 64 + mt * 16 + gr;
        #pragma unroll
        for (int nt = 0; nt < 4; nt++) {
            int c = col0 + wn * 32 + nt * 8 + lc * 2;
            float b0 = bias[c], b1 = bias[c + 1];
            #pragma unroll
            for (int h2 = 0; h2 < 2; h2++) {
                size_t off = (size_t)(r + h2 * 8) * M + c;
                float v0 = acc[mt][nt][h2 * 2 + 0] + b0;
                float v1 = acc[mt][nt][h2 * 2 + 1] + b1;
                if (R) { float2 rv = *(const float2*)(R + off); v0 += rv.x; v1 += rv.y; }
                if (mode == 1) { v0 = fmaxf(v0, 0.f); v1 = fmaxf(v1, 0.f); }
                if (mode == 2) { v0 = tfround(v0); v1 = tfround(v1); }
                *(float2*)(C + off) = make_float2(v0, v1);
            }
        }
    }
}

// ---------------- flash attention v3: V reuses K buffer -> 70KB smem, 3 CTAs/SM ----------------
#define AP 68
#define OQ 0
#define OKB 4352
#define OPS 13056
#define OST 17408
#define ATTN_SMEM ((OST + 192) * 4)

__global__ __launch_bounds__(128) void attn_mma(const float* __restrict__ qkv,
                                                const float* __restrict__ vt,
                                                float* __restrict__ out) {
    extern __shared__ uint32_t smu[];
    uint32_t sb = smem_u32(smu);
    int qt = gridDim.x - 1 - blockIdx.x;        // longest tiles scheduled first
    int bh = blockIdx.y, bb = bh >> 3, hh = bh & 7;
    int t = threadIdx.x, lane = t & 31, wid = t >> 5;
    int gr = lane >> 2, lc = lane & 3;
    int mrow = wid * 16 + gr;
    const size_t base = (size_t)bb * SQ * QKVW + hh * DK;
    const float* qb = qkv + base + (size_t)qt * 64 * QKVW;
    const float* vbase = vt + (size_t)bh * 64 * SQ;

    float* sm_m  = (float*)(smu + OST);
    float* sm_l  = sm_m + 64;
    float* sm_rs = sm_m + 128;
    uint32_t* Qs = smu + OQ;
    float*    Ps = (float*)(smu + OPS);

    // prologue: Q + K0 in one group
    #pragma unroll
    for (int i = 0; i < 8; i++) {
        int f = i * 128 + t, r = f >> 4, d4 = (f & 15) << 2;
        cpa16(sb + (OQ + r * AP + d4) * 4, qb + (size_t)r * QKVW + d4);
    }
    {
        const float* kb = qkv + base + 512;
        #pragma unroll
        for (int i = 0; i < 8; i++) {
            int f = i * 128 + t, r = f >> 4, d4 = (f & 15) << 2;
            cpa16(sb + (OKB + r * AP + d4) * 4, kb + (size_t)r * QKVW + d4);
        }
    }
    CP_COMMIT();

    if (lane < 16) { sm_m[wid * 16 + lane] = -1e30f; sm_l[wid * 16 + lane] = 0.f; }

    float co[8][4];
    #pragma unroll
    for (int i = 0; i < 8; i++)
        #pragma unroll
        for (int j = 0; j < 4; j++) co[i][j] = 0.f;

    for (int kt = 0; kt <= qt; kt++) {
        int cur = kt & 1;
        if (kt == 0) { CP_WAIT(0); __syncthreads(); }   // Q + K0 visible
        const uint32_t* Kb = smu + OKB + cur * 4352;

        // ---- S = Q K^T ----
        float cs[8][4];
        #pragma unroll
        for (int i = 0; i < 8; i++)
            #pragma unroll
            for (int j = 0; j < 4; j++) cs[i][j] = 0.f;
        {
            const uint32_t* Abase = Qs + mrow * AP + lc;
            const uint32_t* Bbase = Kb + gr * AP + lc;
            #pragma unroll
            for (int ks = 0; ks < 8; ks++) {
                uint32_t a[4];
                const uint32_t* p = Abase + ks * 8;
                a[0] = p[0]; a[1] = p[8 * AP]; a[2] = p[4]; a[3] = p[8 * AP + 4];
                #pragma unroll
                for (int nt = 0; nt < 8; nt++) {
                    const uint32_t* q2 = Bbase + nt * 8 * AP + ks * 8;
                    uint32_t b[2] = {q2[0], q2[4]};
                    mma8(cs[nt], a, b);
                }
            }
        }
        #pragma unroll
        for (int nt = 0; nt < 8; nt++) {
            int c = nt * 8 + lc * 2;
            *(float2*)(Ps + mrow * AP + c)       = make_float2(cs[nt][0], cs[nt][1]);
            *(float2*)(Ps + (mrow + 8) * AP + c) = make_float2(cs[nt][2], cs[nt][3]);
        }
        __syncthreads();   // all warps done reading K(kt); Ps visible

        // stage V(kt) into the buffer K(kt) occupied; prefetch K(kt+1) into the other
        #pragma unroll
        for (int i = 0; i < 8; i++) {
            int f = i * 128 + t, d = f >> 4, k4 = (f & 15) << 2;
            cpa16(sb + (OKB + cur * 4352 + d * AP + k4) * 4,
                  vbase + (size_t)d * SQ + kt * 64 + k4);
        }
        CP_COMMIT();
        if (kt < qt) {
            const float* kb = qkv + base + 512 + (size_t)(kt + 1) * 64 * QKVW;
            #pragma unroll
            for (int i = 0; i < 8; i++) {
                int f = i * 128 + t, r = f >> 4, d4 = (f & 15) << 2;
                cpa16(sb + (OKB + (cur ^ 1) * 4352 + r * AP + d4) * 4,
                      kb + (size_t)r * QKVW + d4);
            }
            CP_COMMIT();
        }

        // ---- online softmax (thread pair per row; all intra-warp) ----
        {
            int r = t >> 1, half = t & 1;
            int qrow = qt * 64 + r;
            int kbase0 = kt * 64 + half * 32;
            float* rowp = Ps + r * AP + half * 32;
            float vals[32];
            float mx = -1e30f;
            bool edge = (kt == qt);
            #pragma unroll
            for (int j = 0; j < 32; j += 4) {
                float4 v4 = *(const float4*)(rowp + j);
                float w0 = v4.x * 0.125f, w1 = v4.y * 0.125f;
                float w2 = v4.z * 0.125f, w3 = v4.w * 0.125f;
                if (edge) {
                    if (kbase0 + j + 0 > qrow) w0 = -1e30f;
                    if (kbase0 + j + 1 > qrow) w1 = -1e30f;
                    if (kbase0 + j + 2 > qrow) w2 = -1e30f;
                    if (kbase0 + j + 3 > qrow) w3 = -1e30f;
                }
                vals[j] = w0; vals[j+1] = w1; vals[j+2] = w2; vals[j+3] = w3;
                mx = fmaxf(mx, fmaxf(fmaxf(w0, w1), fmaxf(w2, w3)));
            }
            mx = fmaxf(mx, __shfl_xor_sync(0xffffffffu, mx, 1));
            float mo = sm_m[r];
            float mn = fmaxf(mo, mx);
            float rs = __expf(mo - mn);
            float ssum = 0.f;
            #pragma unroll
            for (int j = 0; j < 32; j += 4) {
                float p0 = __expf(vals[j]   - mn), p1 = __expf(vals[j+1] - mn);
                float p2 = __expf(vals[j+2] - mn), p3 = __expf(vals[j+3] - mn);
                ssum += (p0 + p1) + (p2 + p3);
                *(uint4*)(rowp + j) = make_uint4(f2tf(p0), f2tf(p1), f2tf(p2), f2tf(p3));
            }
            ssum += __shfl_xor_sync(0xffffffffu, ssum, 1);
            if (!half) { sm_l[r] = sm_l[r] * rs + ssum; sm_m[r] = mn; sm_rs[r] = rs; }
        }

        CP_WAIT(0);        // V(kt) (and K(kt+1)) arrived
        __syncthreads();   // V + P visible to all warps

        // ---- O = O*rs + P V ----
        {
            float rs0 = sm_rs[mrow], rs1 = sm_rs[mrow + 8];
            #pragma unroll
            for (int nt = 0; nt < 8; nt++) {
                co[nt][0] *= rs0; co[nt][1] *= rs0;
                co[nt][2] *= rs1; co[nt][3] *= rs1;
            }
            const uint32_t* Pb = (const uint32_t*)Ps + mrow * AP + lc;
            const uint32_t* Bbase = Kb + gr * AP + lc;     // V now lives here
            #pragma unroll
            for (int ks = 0; ks < 8; ks++) {
                uint32_t a[4];
                const uint32_t* p = Pb + ks * 8;
                a[0] = p[0]; a[1] = p[8 * AP]; a[2] = p[4]; a[3] = p[8 * AP + 4];
                #pragma unroll
                for (int nt = 0; nt < 8; nt++) {
                    const uint32_t* q2 = Bbase + nt * 8 * AP + ks * 8;
                    uint32_t b[2] = {q2[0], q2[4]};
                    mma8(co[nt], a, b);
                }
            }
        }
    }

    float inv0 = 1.f / sm_l[mrow], inv1 = 1.f / sm_l[mrow + 8];
    float* ob = out + ((size_t)bb * SQ + (size_t)qt * 64) * DM + hh * DK;
    #pragma unroll
    for (int nt = 0; nt < 8; nt++) {
        int c = nt * 8 + lc * 2;
        *(float2*)(ob + (size_t)mrow * DM + c) =
            make_float2(co[nt][0] * inv0, co[nt][1] * inv0);
        *(float2*)(ob + (size_t)(mrow + 8) * DM + c) =
            make_float2(co[nt][2] * inv1, co[nt][3] * inv1);
    }
}

// ---------------- V pre-transpose ----------------
__global__ __launch_bounds__(256) void vtrans(const float* __restrict__ qkv,
                                              float* __restrict__ vt) {
    __shared__ float tb[32][33];
    int bhid = blockIdx.z, bb = bhid >> 3, hh = bhid & 7;
    int s0 = blockIdx.x * 32, d0 = blockIdx.y * 32;
    const float* in = qkv + (size_t)bb * SQ * QKVW + 1024 + hh * 64;
    float* outp = vt + (size_t)bhid * 64 * SQ;
    int tx = threadIdx.x, ty = threadIdx.y;
    #pragma unroll
    for (int i = 0; i < 32; i += 8)
        tb[ty + i][tx] = in[(size_t)(s0 + ty + i) * QKVW + d0 + tx];
    __syncthreads();
    #pragma unroll
    for (int i = 0; i < 32; i += 8)
        outp[(size_t)(d0 + ty + i) * SQ + s0 + tx] = tb[tx][ty + i];
}

// ---------------- weight transposes ----------------
__global__ __launch_bounds__(256) void transpose_k(const float* __restrict__ in,
                                                   float* __restrict__ out,
                                                   int R, int C,
                                                   size_t in_z, size_t out_z) {
    __shared__ float tbuf[32][33];
    in  += blockIdx.z * in_z;
    out += blockIdx.z * out_z;
    int c0 = blockIdx.x * 32, r0 = blockIdx.y * 32;
    #pragma unroll
    for (int i = 0; i < 32; i += 8)
        tbuf[threadIdx.y + i][threadIdx.x] = in[(size_t)(r0 + threadIdx.y + i) * C + c0 + threadIdx.x];
    __syncthreads();
    #pragma unroll
    for (int i = 0; i < 32; i += 8)
        out[(size_t)(c0 + threadIdx.y + i) * R + r0 + threadIdx.x] = tbuf[threadIdx.x][threadIdx.y + i];
}

// fused q/k/v transpose: one launch, z = layer*3 + {q,k,v}
__global__ __launch_bounds__(256) void transpose_qkv(const float* __restrict__ wq,
                                                     const float* __restrict__ wk,
                                                     const float* __restrict__ wv,
                                                     float* __restrict__ outT) {
    __shared__ float tbuf[32][33];
    int z = blockIdx.z, l = z / 3, w = z % 3;
    const float* in = (w == 0 ? wq : w == 1 ? wk : wv) + (size_t)l * DM * DM;
    float* out = outT + (size_t)l * QKVW * DM + (size_t)w * DM * DM;
    int c0 = blockIdx.x * 32, r0 = blockIdx.y * 32;
    #pragma unroll
    for (int i = 0; i < 32; i += 8)
        tbuf[threadIdx.y + i][threadIdx.x] = in[(size_t)(r0 + threadIdx.y + i) * DM + c0 + threadIdx.x];
    __syncthreads();
    #pragma unroll
    for (int i = 0; i < 32; i += 8)
        out[(size_t)(c0 + threadIdx.y + i) * DM + r0 + threadIdx.x] = tbuf[threadIdx.x][threadIdx.y + i];
}

__global__ __launch_bounds__(256) void biaspack_kernel(const float* __restrict__ bq,
                                                       const float* __restrict__ bk,
                                                       const float* __restrict__ bv,
                                                       float* __restrict__ dst) {
    int idx = blockIdx.x * 256 + threadIdx.x;
    if (idx >= NL * QKVW) return;
    int l = idx / QKVW, j = idx % QKVW;
    float v;
    if (j < 512)       v = bq[l * 512 + j];
    else if (j < 1024) v = bk[l * 512 + j - 512];
    else               v = bv[l * 512 + j - 1024];
    dst[idx] = v;
}

__global__ __launch_bounds__(256) void embed_kernel(const int* __restrict__ ids,
                                                    const float* __restrict__ emb,
                                                    float* __restrict__ x) {
    int idx = blockIdx.x * 256 + threadIdx.x;
    if (idx >= NTOK * DM) return;
    int row = idx >> 9, d = idx & 511, s = row & (SQ - 1);
    int tok = ids[row];
    int i2 = d & ~1;
    float div = expf(-(float)i2 * (9.210340371976184f / 512.0f));
    float ang = (float)s * div;
    float pe = (d & 1) ? cosf(ang) : sinf(ang);
    x[idx] = emb[(size_t)tok * DM + d] + pe;
}

__global__ __launch_bounds__(256) void ln_kernel(const float* __restrict__ x,
                                                 const float* __restrict__ w,
                                                 const float* __restrict__ bias,
                                                 float* __restrict__ y) {
    __shared__ float sred[16];
    int row = blockIdx.x;
    int t = threadIdx.x;
    const float* xr = x + (size_t)row * DM;
    float v0 = xr[t];
    float v1 = xr[t + 256];
    float s = v0 + v1;
    #pragma unroll
    for (int off = 16; off; off >>= 1) s += __shfl_xor_sync(0xffffffffu, s, off);
    if ((t & 31) == 0) sred[t >> 5] = s;
    __syncthreads();
    float tot = 0.f;
    #pragma unroll
    for (int i = 0; i < 8; i++) tot += sred[i];
    float mu = tot * (1.0f / DM);
    float d0 = v0 - mu, d1 = v1 - mu;
    float s2 = d0 * d0 + d1 * d1;
    #pragma unroll
    for (int off = 16; off; off >>= 1) s2 += __shfl_xor_sync(0xffffffffu, s2, off);
    if ((t & 31) == 0) sred[8 + (t >> 5)] = s2;
    __syncthreads();
    float tot2 = 0.f;
    #pragma unroll
    for (int i = 0; i < 8; i++) tot2 += sred[8 + i];
    float var = tot2 * (1.0f / DM);
    float rstd = rsqrtf(var + 1e-5f);
    float* yr = y + (size_t)row * DM;
    yr[t]       = d0 * rstd * w[t]       + bias[t];
    yr[t + 256] = d1 * rstd * w[t + 256] + bias[t + 256];
}

// ---------------- host ----------------
static void run_gemm(const float* A, const float* Wt, const float* bias, const float* R,
                     float* C, int K, int M, int mode) {
    mma_gemm<<<dim3(M / 128, NTOK / 128), 256, GEMM_SMEM>>>(A, Wt, bias, R, C, K, M, mode);
}

extern "C" void kernel_launch(void* const* d_in, const int* in_sizes, int n_in,
                              void* d_out, int out_size) {
    (void)in_sizes; (void)n_in; (void)out_size;
    const int*   ids  = (const int*)  d_in[0];
    const float* emb  = (const float*)d_in[1];
    const float* wq   = (const float*)d_in[2];
    const float* bq   = (const float*)d_in[3];
    const float* wk   = (const float*)d_in[4];
    const float* bk   = (const float*)d_in[5];
    const float* wv   = (const float*)d_in[6];
    const float* bv   = (const float*)d_in[7];
    const float* wo   = (const float*)d_in[8];
    const float* bo   = (const float*)d_in[9];
    const float* ln1w = (const float*)d_in[10];
    const float* ln1b = (const float*)d_in[11];
    const float* ln2w = (const float*)d_in[12];
    const float* ln2b = (const float*)d_in[13];
    const float* w1   = (const float*)d_in[14];
    const float* b1   = (const float*)d_in[15];
    const float* w2   = (const float*)d_in[16];
    const float* b2   = (const float*)d_in[17];
    const float* outw = (const float*)d_in[18];
    const float* outb = (const float*)d_in[19];

    float *x, *h, *qkv, *ff, *vt, *wqkvT, *woT, *w1T, *w2T, *outwT, *bqkv;
    cudaGetSymbolAddress((void**)&x,     g_x);
    cudaGetSymbolAddress((void**)&h,     g_h);
    cudaGetSymbolAddress((void**)&qkv,   g_qkv);
    cudaGetSymbolAddress((void**)&ff,    g_ff);
    cudaGetSymbolAddress((void**)&vt,    g_vt);
    cudaGetSymbolAddress((void**)&wqkvT, g_wqkvT);
    cudaGetSymbolAddress((void**)&woT,   g_woT);
    cudaGetSymbolAddress((void**)&w1T,   g_w1T);
    cudaGetSymbolAddress((void**)&w2T,   g_w2T);
    cudaGetSymbolAddress((void**)&outwT, g_outwT);
    cudaGetSymbolAddress((void**)&bqkv,  g_bqkv);

    cudaFuncSetAttribute(mma_gemm, cudaFuncAttributeMaxDynamicSharedMemorySize, GEMM_SMEM);
    cudaFuncSetAttribute(attn_mma, cudaFuncAttributeMaxDynamicSharedMemorySize, ATTN_SMEM);

    dim3 tb(32, 8);

    // Launch order puts the layer-0 QKV GEMM at launch #6 so ncu (-s 5 -c 1) captures it.
    embed_kernel<<<(NTOK * DM) / 256, 256>>>(ids, emb, x);                      // 1
    transpose_qkv<<<dim3(16, 16, 3 * NL), tb>>>(wq, wk, wv, wqkvT);             // 2
    biaspack_kernel<<<(NL * QKVW + 255) / 256, 256>>>(bq, bk, bv, bqkv);        // 3
    ln_kernel<<<NTOK, 256>>>(x, ln1w, ln1b, h);                                 // 4 (layer 0 ln1)
    transpose_k<<<dim3(16, 16, NL), tb>>>(wo, woT, DM, DM, (size_t)DM*DM, (size_t)DM*DM); // 5
    run_gemm(h, wqkvT, bqkv, nullptr, qkv, DM, QKVW, 2);                        // 6 <- ncu capture
    transpose_k<<<dim3(DFF/32, 16, NL), tb>>>(w1, w1T, DM, DFF, (size_t)DM*DFF, (size_t)DM*DFF);
    transpose_k<<<dim3(16, DFF/32, NL), tb>>>(w2, w2T, DFF, DM, (size_t)DM*DFF, (size_t)DM*DFF);
    transpose_k<<<dim3(NV/32, 16, 1),   tb>>>(outw, outwT, DM, NV, 0, 0);

    for (int l = 0; l < NL; l++) {
        size_t offD = (size_t)l * DM;
        size_t offF = (size_t)l * DFF;

        if (l > 0) {
            ln_kernel<<<NTOK, 256>>>(x, ln1w + offD, ln1b + offD, h);
            run_gemm(h, wqkvT + (size_t)l * QKVW * DM, bqkv + (size_t)l * QKVW, nullptr,
                     qkv, DM, QKVW, 2);
        }
        vtrans<<<dim3(SQ / 32, 2, NB * NH), tb>>>(qkv, vt);
        attn_mma<<<dim3(SQ / 64, NB * NH), 128, ATTN_SMEM>>>(qkv, vt, h);
        run_gemm(h, woT + (size_t)l * DM * DM, bo + offD, nullptr, x, DM, DM, 0);
        ln_kernel<<<NTOK, 256>>>(x, ln2w + offD, ln2b + offD, h);
        run_gemm(h, w1T + (size_t)l * DM * DFF, b1 + offF, nullptr, ff, DM, DFF, 1);
        run_gemm(ff, w2T + (size_t)l * DM * DFF, b2 + offD, x /*residual*/, x, DFF, DM, 0);
    }

    run_gemm(x, outwT, outb, nullptr, (float*)d_out, DM, NV, 0);
}

// round 12
// speedup vs baseline: 2.4341x; 1.0153x over previous
#include <cuda_runtime.h>
#include <math.h>
#include <stdint.h>

#define NB 2
#define SQ 2048
#define NTOK 4096
#define DM 512
#define NH 8
#define DK 64
#define NL 6
#define DFF 2048
#define NV 1024
#define QKVW 1536

// ---------------- scratch ----------------
__device__ float g_x   [NTOK * DM];
__device__ float g_h   [NTOK * DM];
__device__ float g_qkv [NTOK * QKVW];
__device__ float g_ff  [NTOK * DFF];
__device__ float g_vt  [16 * 64 * SQ];          // per (b,h): V transposed [d][s]
__device__ float g_wqkvT[NL * QKVW * DM];
__device__ float g_woT  [NL * DM * DM];
__device__ float g_w1T  [NL * DFF * DM];
__device__ float g_w2T  [NL * DM * DFF];
__device__ float g_outwT[NV * DM];
__device__ float g_bqkv [NL * QKVW];

// ---------------- helpers ----------------
__device__ __forceinline__ uint32_t f2tf(float f) {
    uint32_t r;
    asm("cvt.rna.tf32.f32 %0, %1;" : "=r"(r) : "f"(f));
    return r;
}
__device__ __forceinline__ float tfround(float f) { return __uint_as_float(f2tf(f)); }
__device__ __forceinline__ void mma8(float* c, const uint32_t* a, const uint32_t* b) {
    asm volatile(
        "mma.sync.aligned.m16n8k8.row.col.f32.tf32.tf32.f32 "
        "{%0,%1,%2,%3}, {%4,%5,%6,%7}, {%8,%9}, {%0,%1,%2,%3};\n"
        : "+f"(c[0]), "+f"(c[1]), "+f"(c[2]), "+f"(c[3])
        : "r"(a[0]), "r"(a[1]), "r"(a[2]), "r"(a[3]), "r"(b[0]), "r"(b[1]));
}
__device__ __forceinline__ void cpa16(uint32_t dst, const void* src) {
    asm volatile("cp.async.cg.shared.global [%0], [%1], 16;" :: "r"(dst), "l"(src));
}
#define CP_COMMIT() asm volatile("cp.async.commit_group;" ::: "memory")
#define CP_WAIT(n)  asm volatile("cp.async.wait_group %0;" :: "n"(n) : "memory")
__device__ __forceinline__ uint32_t smem_u32(const void* p) {
    uint32_t a;
    asm("{ .reg .u64 t; cvta.to.shared.u64 t, %1; cvt.u32.u64 %0, t; }" : "=r"(a) : "l"(p));
    return a;
}

// ---------------- tf32 mma GEMM + mode epilogue (+ fused V-transpose) ----------------
#define GP 36
#define GSTAGE 9216
#define GEMM_SMEM (2 * GSTAGE * 4)

__global__ __launch_bounds__(256) void mma_gemm(const float* __restrict__ A,
                                                const float* __restrict__ Wt,
                                                const float* __restrict__ bias,
                                                const float* __restrict__ R,
                                                float* __restrict__ C,
                                                float* __restrict__ VT,
                                                int K, int M, int mode) {
    extern __shared__ uint32_t sm[];
    int t = threadIdx.x, lane = t & 31, wid = t >> 5;
    int wm = wid & 1, wn = wid >> 1;
    int gr = lane >> 2, lc = lane & 3;
    int row0 = blockIdx.y * 128, col0 = blockIdx.x * 128;
    const int NC = K >> 5;

    float acc[4][4][4];
    #pragma unroll
    for (int i = 0; i < 4; i++)
        #pragma unroll
        for (int j = 0; j < 4; j++)
            #pragma unroll
            for (int k = 0; k < 4; k++) acc[i][j][k] = 0.f;

    float4 ra[4], rb[4];
    #pragma unroll
    for (int i = 0; i < 4; i++) {
        int idx = i * 256 + t, r = idx >> 3, c = (idx & 7) << 2;
        ra[i] = *(const float4*)(A  + (size_t)(row0 + r) * K + c);
        rb[i] = *(const float4*)(Wt + (size_t)(col0 + r) * K + c);
    }
    {
        uint32_t* Ab = sm;
        uint32_t* Bb = sm + 4608;
        #pragma unroll
        for (int i = 0; i < 4; i++) {
            int idx = i * 256 + t, r = idx >> 3, c = (idx & 7) << 2, off = r * GP + c;
            *(uint4*)(Ab + off) = make_uint4(f2tf(ra[i].x), f2tf(ra[i].y), f2tf(ra[i].z), f2tf(ra[i].w));
            *(uint4*)(Bb + off) = make_uint4(f2tf(rb[i].x), f2tf(rb[i].y), f2tf(rb[i].z), f2tf(rb[i].w));
        }
    }
    __syncthreads();

    for (int cch = 0; cch < NC; cch++) {
        if (cch + 1 < NC) {
            int k0 = (cch + 1) << 5;
            #pragma unroll
            for (int i = 0; i < 4; i++) {
                int idx = i * 256 + t, r = idx >> 3, c = (idx & 7) << 2;
                ra[i] = *(const float4*)(A  + (size_t)(row0 + r) * K + k0 + c);
                rb[i] = *(const float4*)(Wt + (size_t)(col0 + r) * K + k0 + c);
            }
        }
        {
            const uint32_t* Ab = sm + (cch & 1) * GSTAGE;
            const uint32_t* Bb = Ab + 4608;
            const uint32_t* Abase = Ab + (wm * 64 + gr) * GP + lc;
            const uint32_t* Bbase = Bb + (wn * 32 + gr) * GP + lc;
            #pragma unroll
            for (int ks = 0; ks < 4; ks++) {
                uint32_t a[4][4], b[4][2];
                #pragma unroll
                for (int mt = 0; mt < 4; mt++) {
                    const uint32_t* p = Abase + mt * 16 * GP + ks * 8;
                    a[mt][0] = p[0]; a[mt][1] = p[8 * GP]; a[mt][2] = p[4]; a[mt][3] = p[8 * GP + 4];
                }
                #pragma unroll
                for (int nt = 0; nt < 4; nt++) {
                    const uint32_t* p = Bbase + nt * 8 * GP + ks * 8;
                    b[nt][0] = p[0]; b[nt][1] = p[4];
                }
                #pragma unroll
                for (int mt = 0; mt < 4; mt++)
                    #pragma unroll
                    for (int nt = 0; nt < 4; nt++)
                        mma8(acc[mt][nt], a[mt], b[nt]);
            }
        }
        if (cch + 1 < NC) {
            __syncthreads();
            uint32_t* Ab = sm + ((cch + 1) & 1) * GSTAGE;
            uint32_t* Bb = Ab + 4608;
            #pragma unroll
            for (int i = 0; i < 4; i++) {
                int idx = i * 256 + t, r = idx >> 3, c = (idx & 7) << 2, off = r * GP + c;
                *(uint4*)(Ab + off) = make_uint4(f2tf(ra[i].x), f2tf(ra[i].y), f2tf(ra[i].z), f2tf(ra[i].w));
                *(uint4*)(Bb + off) = make_uint4(f2tf(rb[i].x), f2tf(rb[i].y), f2tf(rb[i].z), f2tf(rb[i].w));
            }
            __syncthreads();
        }
    }

    bool vcols = (VT != nullptr) && (col0 >= 1024);   // CTA-uniform
    #pragma unroll
    for (int mt = 0; mt < 4; mt++) {
        int r = row0 + wm * 64 + mt * 16 + gr;
        #pragma unroll
        for (int nt = 0; nt < 4; nt++) {
            int c = col0 + wn * 32 + nt * 8 + lc * 2;
            float b0 = bias[c], b1 = bias[c + 1];
            #pragma unroll
            for (int h2 = 0; h2 < 2; h2++) {
                int rr = r + h2 * 8;
                size_t off = (size_t)rr * M + c;
                float v0 = acc[mt][nt][h2 * 2 + 0] + b0;
                float v1 = acc[mt][nt][h2 * 2 + 1] + b1;
                if (R) { float2 rv = *(const float2*)(R + off); v0 += rv.x; v1 += rv.y; }
                if (mode == 1) { v0 = fmaxf(v0, 0.f); v1 = fmaxf(v1, 0.f); }
                if (mode == 2) { v0 = tfround(v0); v1 = tfround(v1); }
                if (!vcols) {
                    *(float2*)(C + off) = make_float2(v0, v1);
                } else {
                    // V section: write transposed into vt[bh][d][s]; qkv store is dead.
                    int bbq = rr >> 11, s = rr & (SQ - 1);
                    int dc = c - 1024;
                    int hv = dc >> 6, d = dc & 63;
                    float* vp = VT + ((size_t)((bbq << 3) + hv) * 64 + d) * SQ + s;
                    vp[0]  = v0;
                    vp[SQ] = v1;
                }
            }
        }
    }
}

// ---------------- flash attention v3 (R9-proven, unchanged) ----------------
#define AP 68
#define OQ 0
#define OKB 4352
#define OPS 13056
#define OST 17408
#define ATTN_SMEM ((OST + 192) * 4)

__global__ __launch_bounds__(128) void attn_mma(const float* __restrict__ qkv,
                                                const float* __restrict__ vt,
                                                float* __restrict__ out) {
    extern __shared__ uint32_t smu[];
    uint32_t sb = smem_u32(smu);
    int qt = gridDim.x - 1 - blockIdx.x;
    int bh = blockIdx.y, bb = bh >> 3, hh = bh & 7;
    int t = threadIdx.x, lane = t & 31, wid = t >> 5;
    int gr = lane >> 2, lc = lane & 3;
    int mrow = wid * 16 + gr;
    const size_t base = (size_t)bb * SQ * QKVW + hh * DK;
    const float* qb = qkv + base + (size_t)qt * 64 * QKVW;
    const float* vbase = vt + (size_t)bh * 64 * SQ;

    float* sm_m  = (float*)(smu + OST);
    float* sm_l  = sm_m + 64;
    float* sm_rs = sm_m + 128;
    uint32_t* Qs = smu + OQ;
    float*    Ps = (float*)(smu + OPS);

    #pragma unroll
    for (int i = 0; i < 8; i++) {
        int f = i * 128 + t, r = f >> 4, d4 = (f & 15) << 2;
        cpa16(sb + (OQ + r * AP + d4) * 4, qb + (size_t)r * QKVW + d4);
    }
    {
        const float* kb = qkv + base + 512;
        #pragma unroll
        for (int i = 0; i < 8; i++) {
            int f = i * 128 + t, r = f >> 4, d4 = (f & 15) << 2;
            cpa16(sb + (OKB + r * AP + d4) * 4, kb + (size_t)r * QKVW + d4);
        }
    }
    CP_COMMIT();

    if (lane < 16) { sm_m[wid * 16 + lane] = -1e30f; sm_l[wid * 16 + lane] = 0.f; }

    float co[8][4];
    #pragma unroll
    for (int i = 0; i < 8; i++)
        #pragma unroll
        for (int j = 0; j < 4; j++) co[i][j] = 0.f;

    for (int kt = 0; kt <= qt; kt++) {
        int cur = kt & 1;
        if (kt == 0) { CP_WAIT(0); __syncthreads(); }
        const uint32_t* Kb = smu + OKB + cur * 4352;

        float cs[8][4];
        #pragma unroll
        for (int i = 0; i < 8; i++)
            #pragma unroll
            for (int j = 0; j < 4; j++) cs[i][j] = 0.f;
        {
            const uint32_t* Abase = Qs + mrow * AP + lc;
            const uint32_t* Bbase = Kb + gr * AP + lc;
            #pragma unroll
            for (int ks = 0; ks < 8; ks++) {
                uint32_t a[4];
                const uint32_t* p = Abase + ks * 8;
                a[0] = p[0]; a[1] = p[8 * AP]; a[2] = p[4]; a[3] = p[8 * AP + 4];
                #pragma unroll
                for (int nt = 0; nt < 8; nt++) {
                    const uint32_t* q2 = Bbase + nt * 8 * AP + ks * 8;
                    uint32_t b[2] = {q2[0], q2[4]};
                    mma8(cs[nt], a, b);
                }
            }
        }
        #pragma unroll
        for (int nt = 0; nt < 8; nt++) {
            int c = nt * 8 + lc * 2;
            *(float2*)(Ps + mrow * AP + c)       = make_float2(cs[nt][0], cs[nt][1]);
            *(float2*)(Ps + (mrow + 8) * AP + c) = make_float2(cs[nt][2], cs[nt][3]);
        }
        __syncthreads();

        #pragma unroll
        for (int i = 0; i < 8; i++) {
            int f = i * 128 + t, d = f >> 4, k4 = (f & 15) << 2;
            cpa16(sb + (OKB + cur * 4352 + d * AP + k4) * 4,
                  vbase + (size_t)d * SQ + kt * 64 + k4);
        }
        CP_COMMIT();
        if (kt < qt) {
            const float* kb = qkv + base + 512 + (size_t)(kt + 1) * 64 * QKVW;
            #pragma unroll
            for (int i = 0; i < 8; i++) {
                int f = i * 128 + t, r = f >> 4, d4 = (f & 15) << 2;
                cpa16(sb + (OKB + (cur ^ 1) * 4352 + r * AP + d4) * 4,
                      kb + (size_t)r * QKVW + d4);
            }
            CP_COMMIT();
        }

        {
            int r = t >> 1, half = t & 1;
            int qrow = qt * 64 + r;
            int kbase0 = kt * 64 + half * 32;
            float* rowp = Ps + r * AP + half * 32;
            float vals[32];
            float mx = -1e30f;
            bool edge = (kt == qt);
            #pragma unroll
            for (int j = 0; j < 32; j += 4) {
                float4 v4 = *(const float4*)(rowp + j);
                float w0 = v4.x * 0.125f, w1 = v4.y * 0.125f;
                float w2 = v4.z * 0.125f, w3 = v4.w * 0.125f;
                if (edge) {
                    if (kbase0 + j + 0 > qrow) w0 = -1e30f;
                    if (kbase0 + j + 1 > qrow) w1 = -1e30f;
                    if (kbase0 + j + 2 > qrow) w2 = -1e30f;
                    if (kbase0 + j + 3 > qrow) w3 = -1e30f;
                }
                vals[j] = w0; vals[j+1] = w1; vals[j+2] = w2; vals[j+3] = w3;
                mx = fmaxf(mx, fmaxf(fmaxf(w0, w1), fmaxf(w2, w3)));
            }
            mx = fmaxf(mx, __shfl_xor_sync(0xffffffffu, mx, 1));
            float mo = sm_m[r];
            float mn = fmaxf(mo, mx);
            float rs = __expf(mo - mn);
            float ssum = 0.f;
            #pragma unroll
            for (int j = 0; j < 32; j += 4) {
                float p0 = __expf(vals[j]   - mn), p1 = __expf(vals[j+1] - mn);
                float p2 = __expf(vals[j+2] - mn), p3 = __expf(vals[j+3] - mn);
                ssum += (p0 + p1) + (p2 + p3);
                *(uint4*)(rowp + j) = make_uint4(f2tf(p0), f2tf(p1), f2tf(p2), f2tf(p3));
            }
            ssum += __shfl_xor_sync(0xffffffffu, ssum, 1);
            if (!half) { sm_l[r] = sm_l[r] * rs + ssum; sm_m[r] = mn; sm_rs[r] = rs; }
        }

        CP_WAIT(0);
        __syncthreads();

        {
            float rs0 = sm_rs[mrow], rs1 = sm_rs[mrow + 8];
            #pragma unroll
            for (int nt = 0; nt < 8; nt++) {
                co[nt][0] *= rs0; co[nt][1] *= rs0;
                co[nt][2] *= rs1; co[nt][3] *= rs1;
            }
            const uint32_t* Pb = (const uint32_t*)Ps + mrow * AP + lc;
            const uint32_t* Bbase = Kb + gr * AP + lc;
            #pragma unroll
            for (int ks = 0; ks < 8; ks++) {
                uint32_t a[4];
                const uint32_t* p = Pb + ks * 8;
                a[0] = p[0]; a[1] = p[8 * AP]; a[2] = p[4]; a[3] = p[8 * AP + 4];
                #pragma unroll
                for (int nt = 0; nt < 8; nt++) {
                    const uint32_t* q2 = Bbase + nt * 8 * AP + ks * 8;
                    uint32_t b[2] = {q2[0], q2[4]};
                    mma8(co[nt], a, b);
                }
            }
        }
    }

    float inv0 = 1.f / sm_l[mrow], inv1 = 1.f / sm_l[mrow + 8];
    float* ob = out + ((size_t)bb * SQ + (size_t)qt * 64) * DM + hh * DK;
    #pragma unroll
    for (int nt = 0; nt < 8; nt++) {
        int c = nt * 8 + lc * 2;
        *(float2*)(ob + (size_t)mrow * DM + c) =
            make_float2(co[nt][0] * inv0, co[nt][1] * inv0);
        *(float2*)(ob + (size_t)(mrow + 8) * DM + c) =
            make_float2(co[nt][2] * inv1, co[nt][3] * inv1);
    }
}

// ---------------- weight transposes ----------------
__global__ __launch_bounds__(256) void transpose_k(const float* __restrict__ in,
                                                   float* __restrict__ out,
                                                   int R, int C,
                                                   size_t in_z, size_t out_z) {
    __shared__ float tbuf[32][33];
    in  += blockIdx.z * in_z;
    out += blockIdx.z * out_z;
    int c0 = blockIdx.x * 32, r0 = blockIdx.y * 32;
    #pragma unroll
    for (int i = 0; i < 32; i += 8)
        tbuf[threadIdx.y + i][threadIdx.x] = in[(size_t)(r0 + threadIdx.y + i) * C + c0 + threadIdx.x];
    __syncthreads();
    #pragma unroll
    for (int i = 0; i < 32; i += 8)
        out[(size_t)(c0 + threadIdx.y + i) * R + r0 + threadIdx.x] = tbuf[threadIdx.x][threadIdx.y + i];
}

__global__ __launch_bounds__(256) void transpose_qkv(const float* __restrict__ wq,
                                                     const float* __restrict__ wk,
                                                     const float* __restrict__ wv,
                                                     float* __restrict__ outT) {
    __shared__ float tbuf[32][33];
    int z = blockIdx.z, l = z / 3, w = z % 3;
    const float* in = (w == 0 ? wq : w == 1 ? wk : wv) + (size_t)l * DM * DM;
    float* out = outT + (size_t)l * QKVW * DM + (size_t)w * DM * DM;
    int c0 = blockIdx.x * 32, r0 = blockIdx.y * 32;
    #pragma unroll
    for (int i = 0; i < 32; i += 8)
        tbuf[threadIdx.y + i][threadIdx.x] = in[(size_t)(r0 + threadIdx.y + i) * DM + c0 + threadIdx.x];
    __syncthreads();
    #pragma unroll
    for (int i = 0; i < 32; i += 8)
        out[(size_t)(c0 + threadIdx.y + i) * DM + r0 + threadIdx.x] = tbuf[threadIdx.x][threadIdx.y + i];
}

__global__ __launch_bounds__(256) void biaspack_kernel(const float* __restrict__ bq,
                                                       const float* __restrict__ bk,
                                                       const float* __restrict__ bv,
                                                       float* __restrict__ dst) {
    int idx = blockIdx.x * 256 + threadIdx.x;
    if (idx >= NL * QKVW) return;
    int l = idx / QKVW, j = idx % QKVW;
    float v;
    if (j < 512)       v = bq[l * 512 + j];
    else if (j < 1024) v = bk[l * 512 + j - 512];
    else               v = bv[l * 512 + j - 1024];
    dst[idx] = v;
}

__global__ __launch_bounds__(256) void embed_kernel(const int* __restrict__ ids,
                                                    const float* __restrict__ emb,
                                                    float* __restrict__ x) {
    int idx = blockIdx.x * 256 + threadIdx.x;
    if (idx >= NTOK * DM) return;
    int row = idx >> 9, d = idx & 511, s = row & (SQ - 1);
    int tok = ids[row];
    int i2 = d & ~1;
    float div = expf(-(float)i2 * (9.210340371976184f / 512.0f));
    float ang = (float)s * div;
    float pe = (d & 1) ? cosf(ang) : sinf(ang);
    x[idx] = emb[(size_t)tok * DM + d] + pe;
}

__global__ __launch_bounds__(256) void ln_kernel(const float* __restrict__ x,
                                                 const float* __restrict__ w,
                                                 const float* __restrict__ bias,
                                                 float* __restrict__ y) {
    __shared__ float sred[16];
    int row = blockIdx.x;
    int t = threadIdx.x;
    const float* xr = x + (size_t)row * DM;
    float v0 = xr[t];
    float v1 = xr[t + 256];
    float s = v0 + v1;
    #pragma unroll
    for (int off = 16; off; off >>= 1) s += __shfl_xor_sync(0xffffffffu, s, off);
    if ((t & 31) == 0) sred[t >> 5] = s;
    __syncthreads();
    float tot = 0.f;
    #pragma unroll
    for (int i = 0; i < 8; i++) tot += sred[i];
    float mu = tot * (1.0f / DM);
    float d0 = v0 - mu, d1 = v1 - mu;
    float s2 = d0 * d0 + d1 * d1;
    #pragma unroll
    for (int off = 16; off; off >>= 1) s2 += __shfl_xor_sync(0xffffffffu, s2, off);
    if ((t & 31) == 0) sred[8 + (t >> 5)] = s2;
    __syncthreads();
    float tot2 = 0.f;
    #pragma unroll
    for (int i = 0; i < 8; i++) tot2 += sred[8 + i];
    float var = tot2 * (1.0f / DM);
    float rstd = rsqrtf(var + 1e-5f);
    float* yr = y + (size_t)row * DM;
    yr[t]       = d0 * rstd * w[t]       + bias[t];
    yr[t + 256] = d1 * rstd * w[t + 256] + bias[t + 256];
}

// ---------------- host ----------------
static void run_gemm(const float* A, const float* Wt, const float* bias, const float* R,
                     float* C, float* VT, int K, int M, int mode) {
    mma_gemm<<<dim3(M / 128, NTOK / 128), 256, GEMM_SMEM>>>(A, Wt, bias, R, C, VT, K, M, mode);
}

extern "C" void kernel_launch(void* const* d_in, const int* in_sizes, int n_in,
                              void* d_out, int out_size) {
    (void)in_sizes; (void)n_in; (void)out_size;
    const int*   ids  = (const int*)  d_in[0];
    const float* emb  = (const float*)d_in[1];
    const float* wq   = (const float*)d_in[2];
    const float* bq   = (const float*)d_in[3];
    const float* wk   = (const float*)d_in[4];
    const float* bk   = (const float*)d_in[5];
    const float* wv   = (const float*)d_in[6];
    const float* bv   = (const float*)d_in[7];
    const float* wo   = (const float*)d_in[8];
    const float* bo   = (const float*)d_in[9];
    const float* ln1w = (const float*)d_in[10];
    const float* ln1b = (const float*)d_in[11];
    const float* ln2w = (const float*)d_in[12];
    const float* ln2b = (const float*)d_in[13];
    const float* w1   = (const float*)d_in[14];
    const float* b1   = (const float*)d_in[15];
    const float* w2   = (const float*)d_in[16];
    const float* b2   = (const float*)d_in[17];
    const float* outw = (const float*)d_in[18];
    const float* outb = (const float*)d_in[19];

    float *x, *h, *qkv, *ff, *vt, *wqkvT, *woT, *w1T, *w2T, *outwT, *bqkv;
    cudaGetSymbolAddress((void**)&x,     g_x);
    cudaGetSymbolAddress((void**)&h,     g_h);
    cudaGetSymbolAddress((void**)&qkv,   g_qkv);
    cudaGetSymbolAddress((void**)&ff,    g_ff);
    cudaGetSymbolAddress((void**)&vt,    g_vt);
    cudaGetSymbolAddress((void**)&wqkvT, g_wqkvT);
    cudaGetSymbolAddress((void**)&woT,   g_woT);
    cudaGetSymbolAddress((void**)&w1T,   g_w1T);
    cudaGetSymbolAddress((void**)&w2T,   g_w2T);
    cudaGetSymbolAddress((void**)&outwT, g_outwT);
    cudaGetSymbolAddress((void**)&bqkv,  g_bqkv);

    cudaFuncSetAttribute(mma_gemm, cudaFuncAttributeMaxDynamicSharedMemorySize, GEMM_SMEM);
    cudaFuncSetAttribute(attn_mma, cudaFuncAttributeMaxDynamicSharedMemorySize, ATTN_SMEM);

    dim3 tb(32, 8);

    embed_kernel<<<(NTOK * DM) / 256, 256>>>(ids, emb, x);
    transpose_qkv<<<dim3(16, 16, 3 * NL), tb>>>(wq, wk, wv, wqkvT);
    biaspack_kernel<<<(NL * QKVW + 255) / 256, 256>>>(bq, bk, bv, bqkv);
    ln_kernel<<<NTOK, 256>>>(x, ln1w, ln1b, h);
    transpose_k<<<dim3(16, 16, NL), tb>>>(wo, woT, DM, DM, (size_t)DM*DM, (size_t)DM*DM);
    run_gemm(h, wqkvT, bqkv, nullptr, qkv, vt, DM, QKVW, 2);        // layer 0 QKV (+fused vtrans)
    transpose_k<<<dim3(DFF/32, 16, NL), tb>>>(w1, w1T, DM, DFF, (size_t)DM*DFF, (size_t)DM*DFF);
    transpose_k<<<dim3(16, DFF/32, NL), tb>>>(w2, w2T, DFF, DM, (size_t)DM*DFF, (size_t)DM*DFF);
    transpose_k<<<dim3(NV/32, 16, 1),   tb>>>(outw, outwT, DM, NV, 0, 0);

    for (int l = 0; l < NL; l++) {
        size_t offD = (size_t)l * DM;
        size_t offF = (size_t)l * DFF;

        if (l > 0) {
            ln_kernel<<<NTOK, 256>>>(x, ln1w + offD, ln1b + offD, h);
            run_gemm(h, wqkvT + (size_t)l * QKVW * DM, bqkv + (size_t)l * QKVW, nullptr,
                     qkv, vt, DM, QKVW, 2);
        }
        attn_mma<<<dim3(SQ / 64, NB * NH), 128, ATTN_SMEM>>>(qkv, vt, h);
        run_gemm(h, woT + (size_t)l * DM * DM, bo + offD, nullptr, x, nullptr, DM, DM, 0);
        ln_kernel<<<NTOK, 256>>>(x, ln2w + offD, ln2b + offD, h);
        run_gemm(h, w1T + (size_t)l * DM * DFF, b1 + offF, nullptr, ff, nullptr, DM, DFF, 1);
        run_gemm(ff, w2T + (size_t)l * DM * DFF, b2 + offD, x /*residual*/, x, nullptr, DFF, DM, 0);
    }

    run_gemm(x, outwT, outb, nullptr, (float*)d_out, nullptr, DM, NV, 0);
}

// round 13
// speedup vs baseline: 2.6179x; 1.0755x over previous
#include <cuda_runtime.h>
#include <math.h>
#include <stdint.h>

#define NB 2
#define SQ 2048
#define NTOK 4096
#define DM 512
#define NH 8
#define DK 64
#define NL 6
#define DFF 2048
#define NV 1024
#define QKVW 1536

// ---------------- scratch ----------------
__device__ float g_x   [NTOK * DM];
__device__ float g_h   [NTOK * DM];
__device__ float g_qkv [NTOK * QKVW];
__device__ float g_ff  [NTOK * DFF];
__device__ float g_vt  [16 * 64 * SQ];
__device__ float g_wqkvT[NL * QKVW * DM];
__device__ float g_woT  [NL * DM * DM];
__device__ float g_w1T  [NL * DFF * DM];
__device__ float g_w2T  [NL * DM * DFF];
__device__ float g_outwT[NV * DM];
__device__ float g_bqkv [NL * QKVW];

// ---------------- helpers ----------------
__device__ __forceinline__ uint32_t f2tf(float f) {
    uint32_t r;
    asm("cvt.rna.tf32.f32 %0, %1;" : "=r"(r) : "f"(f));
    return r;
}
__device__ __forceinline__ float tfround(float f) { return __uint_as_float(f2tf(f)); }
__device__ __forceinline__ void mma8(float* c, const uint32_t* a, const uint32_t* b) {
    asm volatile(
        "mma.sync.aligned.m16n8k8.row.col.f32.tf32.tf32.f32 "
        "{%0,%1,%2,%3}, {%4,%5,%6,%7}, {%8,%9}, {%0,%1,%2,%3};\n"
        : "+f"(c[0]), "+f"(c[1]), "+f"(c[2]), "+f"(c[3])
        : "r"(a[0]), "r"(a[1]), "r"(a[2]), "r"(a[3]), "r"(b[0]), "r"(b[1]));
}
__device__ __forceinline__ void cpa16(uint32_t dst, const void* src) {
    asm volatile("cp.async.cg.shared.global [%0], [%1], 16;" :: "r"(dst), "l"(src));
}
#define CP_COMMIT() asm volatile("cp.async.commit_group;" ::: "memory")
#define CP_WAIT(n)  asm volatile("cp.async.wait_group %0;" :: "n"(n) : "memory")
__device__ __forceinline__ uint32_t smem_u32(const void* p) {
    uint32_t a;
    asm("{ .reg .u64 t; cvta.to.shared.u64 t, %1; cvt.u32.u64 %0, t; }" : "=r"(a) : "l"(p));
    return a;
}

#define GP 36

// ======== GEMM epilogue shared by both kernels ========
// mode: 0 plain, 1 relu+tf32round, 2 tf32round
__device__ __forceinline__ void gemm_epilogue(float acc[4][4][4],
                                              const float* bias, const float* R,
                                              float* C, float* VT,
                                              int row0, int col0, int M, int mode,
                                              int wm, int wn, int gr, int lc) {
    bool vcols = (VT != nullptr) && (col0 >= 1024);
    #pragma unroll
    for (int mt = 0; mt < 4; mt++) {
        int r = row0 + wm * 64 + mt * 16 + gr;
        #pragma unroll
        for (int nt = 0; nt < 4; nt++) {
            int c = col0 + wn * 32 + nt * 8 + lc * 2;
            float b0 = bias[c], b1 = bias[c + 1];
            #pragma unroll
            for (int h2 = 0; h2 < 2; h2++) {
                int rr = r + h2 * 8;
                size_t off = (size_t)rr * M + c;
                float v0 = acc[mt][nt][h2 * 2 + 0] + b0;
                float v1 = acc[mt][nt][h2 * 2 + 1] + b1;
                if (R) { float2 rv = *(const float2*)(R + off); v0 += rv.x; v1 += rv.y; }
                if (mode == 1) {
                    v0 = tfround(fmaxf(v0, 0.f)); v1 = tfround(fmaxf(v1, 0.f));
                } else if (mode == 2) {
                    v0 = tfround(v0); v1 = tfround(v1);
                }
                if (!vcols) {
                    *(float2*)(C + off) = make_float2(v0, v1);
                } else {
                    int bbq = rr >> 11, s = rr & (SQ - 1);
                    int dc = c - 1024;
                    int hv = dc >> 6, d = dc & 63;
                    float* vp = VT + ((size_t)((bbq << 3) + hv) * 64 + d) * SQ + s;
                    vp[0]  = v0;
                    vp[SQ] = v1;
                }
            }
        }
    }
}

// ======== cp.async GEMM: A/Wt pre-rounded to tf32 (staging copies raw bits) ========
#define CPSTAGE 9216                    // words per stage (A 4608 + B 4608)
#define GEMM_CP_SMEM (3 * CPSTAGE * 4)  // 110592 B

__global__ __launch_bounds__(256) void gemm_cp(const float* __restrict__ A,
                                               const float* __restrict__ Wt,
                                               const float* __restrict__ bias,
                                               const float* __restrict__ R,
                                               float* __restrict__ C,
                                               float* __restrict__ VT,
                                               int K, int M, int mode) {
    extern __shared__ uint32_t sm[];
    uint32_t sb = smem_u32(sm);
    int t = threadIdx.x, lane = t & 31, wid = t >> 5;
    int wm = wid & 1, wn = wid >> 1;
    int gr = lane >> 2, lc = lane & 3;
    int row0 = blockIdx.y * 128, col0 = blockIdx.x * 128;
    const int NC = K >> 5;

    int half = t >> 7, li = t & 127;
    const float* src = half ? (Wt + (size_t)col0 * K) : (A + (size_t)row0 * K);

    float acc[4][4][4];
    #pragma unroll
    for (int i = 0; i < 4; i++)
        #pragma unroll
        for (int j = 0; j < 4; j++)
            #pragma unroll
            for (int k = 0; k < 4; k++) acc[i][j][k] = 0.f;

    auto issue = [&](int c, int st) {
        uint32_t dbase = sb + (st * CPSTAGE + half * 4608) * 4;
        const float* s0 = src + c * 32;
        #pragma unroll
        for (int j = 0; j < 8; j++) {
            int seg = j * 128 + li, r = seg >> 3, p = seg & 7;
            cpa16(dbase + (r * GP + p * 4) * 4, s0 + (size_t)r * K + p * 4);
        }
    };

    issue(0, 0); CP_COMMIT();
    if (NC > 1) { issue(1, 1); CP_COMMIT(); }

    for (int c = 0; c < NC; c++) {
        if (c + 1 < NC) { CP_WAIT(1); } else { CP_WAIT(0); }
        __syncthreads();
        if (c + 2 < NC) { issue(c + 2, (c + 2) % 3); CP_COMMIT(); }

        const uint32_t* S = sm + (c % 3) * CPSTAGE;
        const uint32_t* Abase = S + (wm * 64 + gr) * GP + lc;
        const uint32_t* Bbase = S + 4608 + (wn * 32 + gr) * GP + lc;
        #pragma unroll
        for (int ks = 0; ks < 4; ks++) {
            uint32_t a[4][4], b[4][2];
            #pragma unroll
            for (int mt = 0; mt < 4; mt++) {
                const uint32_t* p = Abase + mt * 16 * GP + ks * 8;
                a[mt][0] = p[0]; a[mt][1] = p[8 * GP]; a[mt][2] = p[4]; a[mt][3] = p[8 * GP + 4];
            }
            #pragma unroll
            for (int nt = 0; nt < 4; nt++) {
                const uint32_t* p = Bbase + nt * 8 * GP + ks * 8;
                b[nt][0] = p[0]; b[nt][1] = p[4];
            }
            #pragma unroll
            for (int mt = 0; mt < 4; mt++)
                #pragma unroll
                for (int nt = 0; nt < 4; nt++)
                    mma8(acc[mt][nt], a[mt], b[nt]);
        }
        // stage (c+2)%3 was consumed at iter c-1; all threads synced at top of iter c.
    }

    gemm_epilogue(acc, bias, R, C, VT, row0, col0, M, mode, wm, wn, gr, lc);
}

// ======== cvt-staging GEMM (R3-proven) — used only where A isn't pre-rounded ========
#define GSTAGE 9216
#define GEMM_CVT_SMEM (2 * GSTAGE * 4)

__global__ __launch_bounds__(256) void gemm_cvt(const float* __restrict__ A,
                                                const float* __restrict__ Wt,
                                                const float* __restrict__ bias,
                                                const float* __restrict__ R,
                                                float* __restrict__ C,
                                                int K, int M, int mode) {
    extern __shared__ uint32_t sm[];
    int t = threadIdx.x, lane = t & 31, wid = t >> 5;
    int wm = wid & 1, wn = wid >> 1;
    int gr = lane >> 2, lc = lane & 3;
    int row0 = blockIdx.y * 128, col0 = blockIdx.x * 128;
    const int NC = K >> 5;

    float acc[4][4][4];
    #pragma unroll
    for (int i = 0; i < 4; i++)
        #pragma unroll
        for (int j = 0; j < 4; j++)
            #pragma unroll
            for (int k = 0; k < 4; k++) acc[i][j][k] = 0.f;

    float4 ra[4], rb[4];
    #pragma unroll
    for (int i = 0; i < 4; i++) {
        int idx = i * 256 + t, r = idx >> 3, c = (idx & 7) << 2;
        ra[i] = *(const float4*)(A  + (size_t)(row0 + r) * K + c);
        rb[i] = *(const float4*)(Wt + (size_t)(col0 + r) * K + c);
    }
    {
        uint32_t* Ab = sm;
        uint32_t* Bb = sm + 4608;
        #pragma unroll
        for (int i = 0; i < 4; i++) {
            int idx = i * 256 + t, r = idx >> 3, c = (idx & 7) << 2, off = r * GP + c;
            *(uint4*)(Ab + off) = make_uint4(f2tf(ra[i].x), f2tf(ra[i].y), f2tf(ra[i].z), f2tf(ra[i].w));
            *(uint4*)(Bb + off) = make_uint4(f2tf(rb[i].x), f2tf(rb[i].y), f2tf(rb[i].z), f2tf(rb[i].w));
        }
    }
    __syncthreads();

    for (int cch = 0; cch < NC; cch++) {
        if (cch + 1 < NC) {
            int k0 = (cch + 1) << 5;
            #pragma unroll
            for (int i = 0; i < 4; i++) {
                int idx = i * 256 + t, r = idx >> 3, c = (idx & 7) << 2;
                ra[i] = *(const float4*)(A  + (size_t)(row0 + r) * K + k0 + c);
                rb[i] = *(const float4*)(Wt + (size_t)(col0 + r) * K + k0 + c);
            }
        }
        {
            const uint32_t* Ab = sm + (cch & 1) * GSTAGE;
            const uint32_t* Bb = Ab + 4608;
            const uint32_t* Abase = Ab + (wm * 64 + gr) * GP + lc;
            const uint32_t* Bbase = Bb + (wn * 32 + gr) * GP + lc;
            #pragma unroll
            for (int ks = 0; ks < 4; ks++) {
                uint32_t a[4][4], b[4][2];
                #pragma unroll
                for (int mt = 0; mt < 4; mt++) {
                    const uint32_t* p = Abase + mt * 16 * GP + ks * 8;
                    a[mt][0] = p[0]; a[mt][1] = p[8 * GP]; a[mt][2] = p[4]; a[mt][3] = p[8 * GP + 4];
                }
                #pragma unroll
                for (int nt = 0; nt < 4; nt++) {
                    const uint32_t* p = Bbase + nt * 8 * GP + ks * 8;
                    b[nt][0] = p[0]; b[nt][1] = p[4];
                }
                #pragma unroll
                for (int mt = 0; mt < 4; mt++)
                    #pragma unroll
                    for (int nt = 0; nt < 4; nt++)
                        mma8(acc[mt][nt], a[mt], b[nt]);
            }
        }
        if (cch + 1 < NC) {
            __syncthreads();
            uint32_t* Ab = sm + ((cch + 1) & 1) * GSTAGE;
            uint32_t* Bb = Ab + 4608;
            #pragma unroll
            for (int i = 0; i < 4; i++) {
                int idx = i * 256 + t, r = idx >> 3, c = (idx & 7) << 2, off = r * GP + c;
                *(uint4*)(Ab + off) = make_uint4(f2tf(ra[i].x), f2tf(ra[i].y), f2tf(ra[i].z), f2tf(ra[i].w));
                *(uint4*)(Bb + off) = make_uint4(f2tf(rb[i].x), f2tf(rb[i].y), f2tf(rb[i].z), f2tf(rb[i].w));
            }
            __syncthreads();
        }
    }

    gemm_epilogue(acc, bias, R, C, nullptr, row0, col0, M, mode, wm, wn, gr, lc);
}

// ---------------- flash attention v3 (R9-proven; epilogue now tf32-rounds) ----------------
#define AP 68
#define OQ 0
#define OKB 4352
#define OPS 13056
#define OST 17408
#define ATTN_SMEM ((OST + 192) * 4)

__global__ __launch_bounds__(128) void attn_mma(const float* __restrict__ qkv,
                                                const float* __restrict__ vt,
                                                float* __restrict__ out) {
    extern __shared__ uint32_t smu[];
    uint32_t sb = smem_u32(smu);
    int qt = gridDim.x - 1 - blockIdx.x;
    int bh = blockIdx.y, bb = bh >> 3, hh = bh & 7;
    int t = threadIdx.x, lane = t & 31, wid = t >> 5;
    int gr = lane >> 2, lc = lane & 3;
    int mrow = wid * 16 + gr;
    const size_t base = (size_t)bb * SQ * QKVW + hh * DK;
    const float* qb = qkv + base + (size_t)qt * 64 * QKVW;
    const float* vbase = vt + (size_t)bh * 64 * SQ;

    float* sm_m  = (float*)(smu + OST);
    float* sm_l  = sm_m + 64;
    float* sm_rs = sm_m + 128;
    uint32_t* Qs = smu + OQ;
    float*    Ps = (float*)(smu + OPS);

    #pragma unroll
    for (int i = 0; i < 8; i++) {
        int f = i * 128 + t, r = f >> 4, d4 = (f & 15) << 2;
        cpa16(sb + (OQ + r * AP + d4) * 4, qb + (size_t)r * QKVW + d4);
    }
    {
        const float* kb = qkv + base + 512;
        #pragma unroll
        for (int i = 0; i < 8; i++) {
            int f = i * 128 + t, r = f >> 4, d4 = (f & 15) << 2;
            cpa16(sb + (OKB + r * AP + d4) * 4, kb + (size_t)r * QKVW + d4);
        }
    }
    CP_COMMIT();

    if (lane < 16) { sm_m[wid * 16 + lane] = -1e30f; sm_l[wid * 16 + lane] = 0.f; }

    float co[8][4];
    #pragma unroll
    for (int i = 0; i < 8; i++)
        #pragma unroll
        for (int j = 0; j < 4; j++) co[i][j] = 0.f;

    for (int kt = 0; kt <= qt; kt++) {
        int cur = kt & 1;
        if (kt == 0) { CP_WAIT(0); __syncthreads(); }
        const uint32_t* Kb = smu + OKB + cur * 4352;

        float cs[8][4];
        #pragma unroll
        for (int i = 0; i < 8; i++)
            #pragma unroll
            for (int j = 0; j < 4; j++) cs[i][j] = 0.f;
        {
            const uint32_t* Abase = Qs + mrow * AP + lc;
            const uint32_t* Bbase = Kb + gr * AP + lc;
            #pragma unroll
            for (int ks = 0; ks < 8; ks++) {
                uint32_t a[4];
                const uint32_t* p = Abase + ks * 8;
                a[0] = p[0]; a[1] = p[8 * AP]; a[2] = p[4]; a[3] = p[8 * AP + 4];
                #pragma unroll
                for (int nt = 0; nt < 8; nt++) {
                    const uint32_t* q2 = Bbase + nt * 8 * AP + ks * 8;
                    uint32_t b[2] = {q2[0], q2[4]};
                    mma8(cs[nt], a, b);
                }
            }
        }
        #pragma unroll
        for (int nt = 0; nt < 8; nt++) {
            int c = nt * 8 + lc * 2;
            *(float2*)(Ps + mrow * AP + c)       = make_float2(cs[nt][0], cs[nt][1]);
            *(float2*)(Ps + (mrow + 8) * AP + c) = make_float2(cs[nt][2], cs[nt][3]);
        }
        __syncthreads();

        #pragma unroll
        for (int i = 0; i < 8; i++) {
            int f = i * 128 + t, d = f >> 4, k4 = (f & 15) << 2;
            cpa16(sb + (OKB + cur * 4352 + d * AP + k4) * 4,
                  vbase + (size_t)d * SQ + kt * 64 + k4);
        }
        CP_COMMIT();
        if (kt < qt) {
            const float* kb = qkv + base + 512 + (size_t)(kt + 1) * 64 * QKVW;
            #pragma unroll
            for (int i = 0; i < 8; i++) {
                int f = i * 128 + t, r = f >> 4, d4 = (f & 15) << 2;
                cpa16(sb + (OKB + (cur ^ 1) * 4352 + r * AP + d4) * 4,
                      kb + (size_t)r * QKVW + d4);
            }
            CP_COMMIT();
        }

        {
            int r = t >> 1, half = t & 1;
            int qrow = qt * 64 + r;
            int kbase0 = kt * 64 + half * 32;
            float* rowp = Ps + r * AP + half * 32;
            float vals[32];
            float mx = -1e30f;
            bool edge = (kt == qt);
            #pragma unroll
            for (int j = 0; j < 32; j += 4) {
                float4 v4 = *(const float4*)(rowp + j);
                float w0 = v4.x * 0.125f, w1 = v4.y * 0.125f;
                float w2 = v4.z * 0.125f, w3 = v4.w * 0.125f;
                if (edge) {
                    if (kbase0 + j + 0 > qrow) w0 = -1e30f;
                    if (kbase0 + j + 1 > qrow) w1 = -1e30f;
                    if (kbase0 + j + 2 > qrow) w2 = -1e30f;
                    if (kbase0 + j + 3 > qrow) w3 = -1e30f;
                }
                vals[j] = w0; vals[j+1] = w1; vals[j+2] = w2; vals[j+3] = w3;
                mx = fmaxf(mx, fmaxf(fmaxf(w0, w1), fmaxf(w2, w3)));
            }
            mx = fmaxf(mx, __shfl_xor_sync(0xffffffffu, mx, 1));
            float mo = sm_m[r];
            float mn = fmaxf(mo, mx);
            float rs = __expf(mo - mn);
            float ssum = 0.f;
            #pragma unroll
            for (int j = 0; j < 32; j += 4) {
                float p0 = __expf(vals[j]   - mn), p1 = __expf(vals[j+1] - mn);
                float p2 = __expf(vals[j+2] - mn), p3 = __expf(vals[j+3] - mn);
                ssum += (p0 + p1) + (p2 + p3);
                *(uint4*)(rowp + j) = make_uint4(f2tf(p0), f2tf(p1), f2tf(p2), f2tf(p3));
            }
            ssum += __shfl_xor_sync(0xffffffffu, ssum, 1);
            if (!half) { sm_l[r] = sm_l[r] * rs + ssum; sm_m[r] = mn; sm_rs[r] = rs; }
        }

        CP_WAIT(0);
        __syncthreads();

        {
            float rs0 = sm_rs[mrow], rs1 = sm_rs[mrow + 8];
            #pragma unroll
            for (int nt = 0; nt < 8; nt++) {
                co[nt][0] *= rs0; co[nt][1] *= rs0;
                co[nt][2] *= rs1; co[nt][3] *= rs1;
            }
            const uint32_t* Pb = (const uint32_t*)Ps + mrow * AP + lc;
            const uint32_t* Bbase = Kb + gr * AP + lc;
            #pragma unroll
            for (int ks = 0; ks < 8; ks++) {
                uint32_t a[4];
                const uint32_t* p = Pb + ks * 8;
                a[0] = p[0]; a[1] = p[8 * AP]; a[2] = p[4]; a[3] = p[8 * AP + 4];
                #pragma unroll
                for (int nt = 0; nt < 8; nt++) {
                    const uint32_t* q2 = Bbase + nt * 8 * AP + ks * 8;
                    uint32_t b[2] = {q2[0], q2[4]};
                    mma8(co[nt], a, b);
                }
            }
        }
    }

    float inv0 = 1.f / sm_l[mrow], inv1 = 1.f / sm_l[mrow + 8];
    float* ob = out + ((size_t)bb * SQ + (size_t)qt * 64) * DM + hh * DK;
    #pragma unroll
    for (int nt = 0; nt < 8; nt++) {
        int c = nt * 8 + lc * 2;
        *(float2*)(ob + (size_t)mrow * DM + c) =
            make_float2(tfround(co[nt][0] * inv0), tfround(co[nt][1] * inv0));
        *(float2*)(ob + (size_t)(mrow + 8) * DM + c) =
            make_float2(tfround(co[nt][2] * inv1), tfround(co[nt][3] * inv1));
    }
}

// ---------------- weight transposes (now write tf32-rounded values) ----------------
__global__ __launch_bounds__(256) void transpose_k(const float* __restrict__ in,
                                                   float* __restrict__ out,
                                                   int R, int C,
                                                   size_t in_z, size_t out_z) {
    __shared__ float tbuf[32][33];
    in  += blockIdx.z * in_z;
    out += blockIdx.z * out_z;
    int c0 = blockIdx.x * 32, r0 = blockIdx.y * 32;
    #pragma unroll
    for (int i = 0; i < 32; i += 8)
        tbuf[threadIdx.y + i][threadIdx.x] = in[(size_t)(r0 + threadIdx.y + i) * C + c0 + threadIdx.x];
    __syncthreads();
    #pragma unroll
    for (int i = 0; i < 32; i += 8)
        out[(size_t)(c0 + threadIdx.y + i) * R + r0 + threadIdx.x] =
            tfround(tbuf[threadIdx.x][threadIdx.y + i]);
}

__global__ __launch_bounds__(256) void transpose_qkv(const float* __restrict__ wq,
                                                     const float* __restrict__ wk,
                                                     const float* __restrict__ wv,
                                                     float* __restrict__ outT) {
    __shared__ float tbuf[32][33];
    int z = blockIdx.z, l = z / 3, w = z % 3;
    const float* in = (w == 0 ? wq : w == 1 ? wk : wv) + (size_t)l * DM * DM;
    float* out = outT + (size_t)l * QKVW * DM + (size_t)w * DM * DM;
    int c0 = blockIdx.x * 32, r0 = blockIdx.y * 32;
    #pragma unroll
    for (int i = 0; i < 32; i += 8)
        tbuf[threadIdx.y + i][threadIdx.x] = in[(size_t)(r0 + threadIdx.y + i) * DM + c0 + threadIdx.x];
    __syncthreads();
    #pragma unroll
    for (int i = 0; i < 32; i += 8)
        out[(size_t)(c0 + threadIdx.y + i) * DM + r0 + threadIdx.x] =
            tfround(tbuf[threadIdx.x][threadIdx.y + i]);
}

__global__ __launch_bounds__(256) void biaspack_kernel(const float* __restrict__ bq,
                                                       const float* __restrict__ bk,
                                                       const float* __restrict__ bv,
                                                       float* __restrict__ dst) {
    int idx = blockIdx.x * 256 + threadIdx.x;
    if (idx >= NL * QKVW) return;
    int l = idx / QKVW, j = idx % QKVW;
    float v;
    if (j < 512)       v = bq[l * 512 + j];
    else if (j < 1024) v = bk[l * 512 + j - 512];
    else               v = bv[l * 512 + j - 1024];
    dst[idx] = v;
}

__global__ __launch_bounds__(256) void embed_kernel(const int* __restrict__ ids,
                                                    const float* __restrict__ emb,
                                                    float* __restrict__ x) {
    int idx = blockIdx.x * 256 + threadIdx.x;
    if (idx >= NTOK * DM) return;
    int row = idx >> 9, d = idx & 511, s = row & (SQ - 1);
    int tok = ids[row];
    int i2 = d & ~1;
    float div = expf(-(float)i2 * (9.210340371976184f / 512.0f));
    float ang = (float)s * div;
    float pe = (d & 1) ? cosf(ang) : sinf(ang);
    x[idx] = emb[(size_t)tok * DM + d] + pe;
}

// ---------------- layernorm (now writes tf32-rounded values) ----------------
__global__ __launch_bounds__(256) void ln_kernel(const float* __restrict__ x,
                                                 const float* __restrict__ w,
                                                 const float* __restrict__ bias,
                                                 float* __restrict__ y) {
    __shared__ float sred[16];
    int row = blockIdx.x;
    int t = threadIdx.x;
    const float* xr = x + (size_t)row * DM;
    float v0 = xr[t];
    float v1 = xr[t + 256];
    float s = v0 + v1;
    #pragma unroll
    for (int off = 16; off; off >>= 1) s += __shfl_xor_sync(0xffffffffu, s, off);
    if ((t & 31) == 0) sred[t >> 5] = s;
    __syncthreads();
    float tot = 0.f;
    #pragma unroll
    for (int i = 0; i < 8; i++) tot += sred[i];
    float mu = tot * (1.0f / DM);
    float d0 = v0 - mu, d1 = v1 - mu;
    float s2 = d0 * d0 + d1 * d1;
    #pragma unroll
    for (int off = 16; off; off >>= 1) s2 += __shfl_xor_sync(0xffffffffu, s2, off);
    if ((t & 31) == 0) sred[8 + (t >> 5)] = s2;
    __syncthreads();
    float tot2 = 0.f;
    #pragma unroll
    for (int i = 0; i < 8; i++) tot2 += sred[8 + i];
    float var = tot2 * (1.0f / DM);
    float rstd = rsqrtf(var + 1e-5f);
    float* yr = y + (size_t)row * DM;
    yr[t]       = tfround(d0 * rstd * w[t]       + bias[t]);
    yr[t + 256] = tfround(d1 * rstd * w[t + 256] + bias[t + 256]);
}

// ---------------- host ----------------
static void run_gemm_cp(const float* A, const float* Wt, const float* bias, const float* R,
                        float* C, float* VT, int K, int M, int mode) {
    gemm_cp<<<dim3(M / 128, NTOK / 128), 256, GEMM_CP_SMEM>>>(A, Wt, bias, R, C, VT, K, M, mode);
}

extern "C" void kernel_launch(void* const* d_in, const int* in_sizes, int n_in,
                              void* d_out, int out_size) {
    (void)in_sizes; (void)n_in; (void)out_size;
    const int*   ids  = (const int*)  d_in[0];
    const float* emb  = (const float*)d_in[1];
    const float* wq   = (const float*)d_in[2];
    const float* bq   = (const float*)d_in[3];
    const float* wk   = (const float*)d_in[4];
    const float* bk   = (const float*)d_in[5];
    const float* wv   = (const float*)d_in[6];
    const float* bv   = (const float*)d_in[7];
    const float* wo   = (const float*)d_in[8];
    const float* bo   = (const float*)d_in[9];
    const float* ln1w = (const float*)d_in[10];
    const float* ln1b = (const float*)d_in[11];
    const float* ln2w = (const float*)d_in[12];
    const float* ln2b = (const float*)d_in[13];
    const float* w1   = (const float*)d_in[14];
    const float* b1   = (const float*)d_in[15];
    const float* w2   = (const float*)d_in[16];
    const float* b2   = (const float*)d_in[17];
    const float* outw = (const float*)d_in[18];
    const float* outb = (const float*)d_in[19];

    float *x, *h, *qkv, *ff, *vt, *wqkvT, *woT, *w1T, *w2T, *outwT, *bqkv;
    cudaGetSymbolAddress((void**)&x,     g_x);
    cudaGetSymbolAddress((void**)&h,     g_h);
    cudaGetSymbolAddress((void**)&qkv,   g_qkv);
    cudaGetSymbolAddress((void**)&ff,    g_ff);
    cudaGetSymbolAddress((void**)&vt,    g_vt);
    cudaGetSymbolAddress((void**)&wqkvT, g_wqkvT);
    cudaGetSymbolAddress((void**)&woT,   g_woT);
    cudaGetSymbolAddress((void**)&w1T,   g_w1T);
    cudaGetSymbolAddress((void**)&w2T,   g_w2T);
    cudaGetSymbolAddress((void**)&outwT, g_outwT);
    cudaGetSymbolAddress((void**)&bqkv,  g_bqkv);

    cudaFuncSetAttribute(gemm_cp,  cudaFuncAttributeMaxDynamicSharedMemorySize, GEMM_CP_SMEM);
    cudaFuncSetAttribute(gemm_cvt, cudaFuncAttributeMaxDynamicSharedMemorySize, GEMM_CVT_SMEM);
    cudaFuncSetAttribute(attn_mma, cudaFuncAttributeMaxDynamicSharedMemorySize, ATTN_SMEM);

    dim3 tb(32, 8);

    embed_kernel<<<(NTOK * DM) / 256, 256>>>(ids, emb, x);
    transpose_qkv<<<dim3(16, 16, 3 * NL), tb>>>(wq, wk, wv, wqkvT);
    biaspack_kernel<<<(NL * QKVW + 255) / 256, 256>>>(bq, bk, bv, bqkv);
    ln_kernel<<<NTOK, 256>>>(x, ln1w, ln1b, h);
    transpose_k<<<dim3(16, 16, NL), tb>>>(wo, woT, DM, DM, (size_t)DM*DM, (size_t)DM*DM);
    run_gemm_cp(h, wqkvT, bqkv, nullptr, qkv, vt, DM, QKVW, 2);   // layer 0 QKV (+fused vtrans)
    transpose_k<<<dim3(DFF/32, 16, NL), tb>>>(w1, w1T, DM, DFF, (size_t)DM*DFF, (size_t)DM*DFF);
    transpose_k<<<dim3(16, DFF/32, NL), tb>>>(w2, w2T, DFF, DM, (size_t)DM*DFF, (size_t)DM*DFF);
    transpose_k<<<dim3(NV/32, 16, 1),   tb>>>(outw, outwT, DM, NV, 0, 0);

    for (int l = 0; l < NL; l++) {
        size_t offD = (size_t)l * DM;
        size_t offF = (size_t)l * DFF;

        if (l > 0) {
            ln_kernel<<<NTOK, 256>>>(x, ln1w + offD, ln1b + offD, h);
            run_gemm_cp(h, wqkvT + (size_t)l * QKVW * DM, bqkv + (size_t)l * QKVW, nullptr,
                        qkv, vt, DM, QKVW, 2);
        }
        attn_mma<<<dim3(SQ / 64, NB * NH), 128, ATTN_SMEM>>>(qkv, vt, h);
        run_gemm_cp(h, woT + (size_t)l * DM * DM, bo + offD, nullptr, x, nullptr, DM, DM, 0);
        ln_kernel<<<NTOK, 256>>>(x, ln2w + offD, ln2b + offD, h);
        run_gemm_cp(h, w1T + (size_t)l * DM * DFF, b1 + offF, nullptr, ff, nullptr, DM, DFF, 1);
        run_gemm_cp(ff, w2T + (size_t)l * DM * DFF, b2 + offD, x /*residual*/, x, nullptr, DFF, DM, 0);
    }

    // x is NOT tf32-pre-rounded (residual stream) -> cvt-staging kernel for logits
    gemm_cvt<<<dim3(NV / 128, NTOK / 128), 256, GEMM_CVT_SMEM>>>(
        x, outwT, outb, nullptr, (float*)d_out, DM, NV, 0);
}